// round 12
// baseline (speedup 1.0000x reference)
#include <cuda_runtime.h>
#include <cuda_bf16.h>
#include <cstdint>

#define Bc 8
#define Gc 256
#define Nn 1024
#define Pc 4
#define Fc 256
#define Kc 4
#define NBP 32
#define MAXS 128

// ======================= device scratch ======================================
__device__ float g_e1[NBP * Nn];
__device__ float g_e2[NBP * Nn];
__device__ float g_m[NBP * Nn];
__device__ float g_s[NBP * Nn];
__device__ int g_cnt[Bc * Nn];
__device__ unsigned short g_idx[(size_t)Bc * Nn * MAXS];    // 2 MB
__device__ float2 g_avi[(size_t)NBP * Nn * MAXS];           // 32 MB (value, i-bits), zero-padded
__device__ float g_zf[(size_t)NBP * Nn * Nn];               // 128 MB zT fp32 [bp][n][kG]
__device__ __nv_bfloat16 g_zh[(size_t)NBP * Nn * Nn];       // 64 MB zT hi
__device__ __nv_bfloat16 g_zl[(size_t)NBP * Nn * Nn];       // 64 MB zT lo
__device__ __nv_bfloat16 g_fwh[(size_t)Pc * Fc * Kc * Gc];
__device__ __nv_bfloat16 g_fwl[(size_t)Pc * Fc * Kc * Gc];

__device__ __forceinline__ void split2(float v, __nv_bfloat16& h, __nv_bfloat16& l) {
    h = __float2bfloat16(v);
    l = __float2bfloat16(v - __bfloat162float(h));
}

// ======================= helpers =============================================
__device__ __forceinline__ uint32_t smem_u32(const void* p) {
    uint32_t a;
    asm("{ .reg .u64 t; cvta.to.shared.u64 t, %1; cvt.u32.u64 %0, t; }" : "=r"(a) : "l"(p));
    return a;
}
__device__ __forceinline__ void cpa16(uint32_t dst, const void* src) {
    asm volatile("cp.async.cg.shared.global [%0], [%1], 16;" :: "r"(dst), "l"(src));
}
__device__ __forceinline__ void cpa_commit() { asm volatile("cp.async.commit_group;" ::: "memory"); }
__device__ __forceinline__ void cpa_wait2() { asm volatile("cp.async.wait_group 2;" ::: "memory"); }
__device__ __forceinline__ void cpa_wait1() { asm volatile("cp.async.wait_group 1;" ::: "memory"); }
__device__ __forceinline__ void cpa_wait0() { asm volatile("cp.async.wait_group 0;" ::: "memory"); }

#define SWZ(off) ((off) ^ (((off) >> 3) & 0x70))

__device__ __forceinline__ void ldm_x4(uint32_t& r0, uint32_t& r1, uint32_t& r2, uint32_t& r3,
                                       uint32_t addr) {
    asm volatile("ldmatrix.sync.aligned.m8n8.x4.shared.b16 {%0,%1,%2,%3}, [%4];"
                 : "=r"(r0), "=r"(r1), "=r"(r2), "=r"(r3) : "r"(addr));
}
__device__ __forceinline__ void ldm_x2(uint32_t& r0, uint32_t& r1, uint32_t addr) {
    asm volatile("ldmatrix.sync.aligned.m8n8.x2.shared.b16 {%0,%1}, [%2];"
                 : "=r"(r0), "=r"(r1) : "r"(addr));
}
__device__ __forceinline__ void mma16816(float* c, const uint32_t* a, const uint32_t* b) {
    asm volatile(
        "mma.sync.aligned.m16n8k16.row.col.f32.bf16.bf16.f32 "
        "{%0,%1,%2,%3}, {%4,%5,%6,%7}, {%8,%9}, {%0,%1,%2,%3};"
        : "+f"(c[0]), "+f"(c[1]), "+f"(c[2]), "+f"(c[3])
        : "r"(a[0]), "r"(a[1]), "r"(a[2]), "r"(a[3]), "r"(b[0]), "r"(b[1]));
}

// ======================= reductions ==========================================
__device__ __forceinline__ float blockReduceMax(float v, float* sm) {
#pragma unroll
    for (int o = 16; o; o >>= 1) v = fmaxf(v, __shfl_xor_sync(0xffffffffu, v, o));
    if ((threadIdx.x & 31) == 0) sm[threadIdx.x >> 5] = v;
    __syncthreads();
    if (threadIdx.x < 32) {
        float t = (threadIdx.x < 8) ? sm[threadIdx.x] : -3.0e38f;
#pragma unroll
        for (int o = 4; o; o >>= 1) t = fmaxf(t, __shfl_xor_sync(0xffffffffu, t, o));
        if (threadIdx.x == 0) sm[0] = t;
    }
    __syncthreads();
    float r = sm[0];
    __syncthreads();
    return r;
}
__device__ __forceinline__ float blockReduceSum(float v, float* sm) {
#pragma unroll
    for (int o = 16; o; o >>= 1) v += __shfl_xor_sync(0xffffffffu, v, o);
    if ((threadIdx.x & 31) == 0) sm[threadIdx.x >> 5] = v;
    __syncthreads();
    if (threadIdx.x < 32) {
        float t = (threadIdx.x < 8) ? sm[threadIdx.x] : 0.f;
#pragma unroll
        for (int o = 4; o; o >>= 1) t += __shfl_xor_sync(0xffffffffu, t, o);
        if (threadIdx.x == 0) sm[0] = t;
    }
    __syncthreads();
    float r = sm[0];
    __syncthreads();
    return r;
}

// ======================= 1. fused pe + idx =====================================
__global__ void peidx_kernel(const float* __restrict__ x,
                             const float* __restrict__ mixer,
                             const float* __restrict__ weight,
                             const float* __restrict__ wb,
                             const float* __restrict__ S) {
    __shared__ __align__(16) char sbuf[16896];
    int bid = blockIdx.x, tid = threadIdx.x;
    if (bid < 128) {
        int bp = bid >> 2;
        int b = bp >> 2, p = bp & 3;
        float* s1 = (float*)sbuf;
        float* s2 = s1 + Gc;
        float* sc = s2 + Gc;
        {
            int g = tid;
            float v1 = 0.f, v2 = 0.f;
            const float* mw1 = mixer + p * 2 * Fc;
            const float* mw2 = mw1 + Fc;
#pragma unroll 8
            for (int f = 0; f < Fc; ++f) {
                float w = weight[((size_t)(p * Fc + f)) * Gc + g];
                v1 = fmaf(mw1[f], w, v1);
                v2 = fmaf(mw2[f], w, v2);
            }
            s1[g] = v1;
            s2[g] = v2;
            if (g == 0) {
                float c1 = 0.f, c2 = 0.f;
                for (int f = 0; f < Fc; ++f) {
                    c1 = fmaf(mw1[f], wb[p * Fc + f], c1);
                    c2 = fmaf(mw2[f], wb[p * Fc + f], c2);
                }
                sc[0] = c1;
                sc[1] = c2;
            }
        }
        __syncthreads();
        int n = (bid & 3) * 256 + tid;
        const float* xb = x + (size_t)b * Gc * Nn + n;
        float a1 = 0.f, a2 = 0.f;
#pragma unroll 8
        for (int g = 0; g < Gc; ++g) {
            float xv = xb[(size_t)g * Nn];
            a1 = fmaf(s1[g], xv, a1);
            a2 = fmaf(s2[g], xv, a2);
        }
        g_e1[bp * Nn + n] = a1 + sc[0];
        g_e2[bp * Nn + n] = a2 + sc[1];
    } else {
        int fb = bid - 128;
        int b = fb >> 7;
        int w = tid >> 5, lane = tid & 31;
        int j = (fb & 127) * 8 + w;
        unsigned short(*tmp)[1024] = (unsigned short(*)[1024])sbuf;
        const float* Sb = S + (size_t)b * Nn * Nn + j;
        int r0 = lane * 32;
        int c = 0;
#pragma unroll 4
        for (int r = 0; r < 32; ++r) {
            float s = __ldg(Sb + (size_t)(r0 + r) * Nn);
            if (fabsf(s) > 1e-9f) tmp[w][r0 + c++] = (unsigned short)(r0 + r);
        }
        int incl = c;
#pragma unroll
        for (int o = 1; o < 32; o <<= 1) {
            int t = __shfl_up_sync(0xffffffffu, incl, o);
            if (lane >= o) incl += t;
        }
        int excl = incl - c;
        int total = __shfl_sync(0xffffffffu, incl, 31);
        unsigned short* ipout = g_idx + ((size_t)b * Nn + j) * MAXS;
        for (int t = 0; t < c; ++t) {
            int pos = excl + t;
            if (pos < MAXS) ipout[pos] = tmp[w][r0 + t];
        }
        if (lane == 0) g_cnt[b * Nn + j] = total < MAXS ? total : MAXS;
    }
}

// ======================= 2. ms: per-row softmax stats ==========================
__global__ void ms_kernel(const float* __restrict__ S) {
    int i = blockIdx.x, bp = blockIdx.y, b = bp >> 2;
    __shared__ float sm[8];
    float e2i = g_e2[bp * Nn + i];
    const float* e1r = g_e1 + bp * Nn;
    const float* Sr = S + (size_t)b * Nn * Nn + (size_t)i * Nn;
    float lv[4];
    int mk[4];
    float vmax = -3.0e38f;
#pragma unroll
    for (int q = 0; q < 4; ++q) {
        int j = threadIdx.x + q * 256;
        float s = Sr[j];
        int m = (fabsf(s) > 1e-9f);
        float e = e1r[j] + e2i;
        float l = e > 0.f ? e : 0.2f * e;
        lv[q] = l;
        mk[q] = m;
        if (m) vmax = fmaxf(vmax, l);
    }
    vmax = blockReduceMax(vmax, sm);
    float sum = 0.f;
#pragma unroll
    for (int q = 0; q < 4; ++q)
        sum += mk[q] ? __expf(lv[q] - vmax) : 0.f;
    sum = blockReduceSum(sum, sm);
    if (threadIdx.x == 0) {
        g_m[bp * Nn + i] = vmax;
        g_s[bp * Nn + i] = sum;
    }
}

// ======================= 3. fused fill + split =================================
__global__ void fillsplit_kernel(const float* __restrict__ x, const float* __restrict__ fw) {
    __shared__ float t[32][33];
    int bid = blockIdx.x, tid = threadIdx.x;
    if (bid < 4096) {
        int bp = bid >> 7, b = bp >> 2;
        int w = tid >> 5, lane = tid & 31;
        int j = (bid & 127) * 8 + w;
        int cnt = g_cnt[b * Nn + j];
        float e1j = g_e1[bp * Nn + j];
        const unsigned short* ip = g_idx + ((size_t)b * Nn + j) * MAXS;
        float2* ap = g_avi + ((size_t)bp * Nn + j) * MAXS;
#pragma unroll
        for (int s = lane; s < MAXS; s += 32) {
            float2 o = make_float2(0.f, __int_as_float(0));
            if (s < cnt) {
                int i = ip[s];
                float e = e1j + g_e2[bp * Nn + i];
                float l = e > 0.f ? e : 0.2f * e;
                o = make_float2(__expf(l - g_m[bp * Nn + i]) / g_s[bp * Nn + i], __int_as_float(i));
            }
            ap[s] = o;
        }
    } else {
        int sbid = bid - 4096;
        int b = sbid >> 8;
        int g0 = ((sbid >> 5) & 7) * 32, n0 = (sbid & 31) * 32;
        int tx = tid & 31, ty = tid >> 5;
        const float* xp = x + ((size_t)b * Gc + g0) * Nn + n0;
#pragma unroll
        for (int q = 0; q < 4; ++q) {
            int g = ty + q * 8;
            t[g][tx] = xp[(size_t)g * Nn + tx];
        }
        __syncthreads();
#pragma unroll
        for (int q = 0; q < 4; ++q) {
            int nn = ty + q * 8;
            float v = t[tx][nn];
            __nv_bfloat16 h, l;
            split2(v, h, l);
#pragma unroll
            for (int p = 0; p < 4; ++p) {
                size_t o = (((size_t)(b * 4 + p) * Nn) + n0 + nn) * Nn + g0 + tx;
                g_zf[o] = v;
                g_zh[o] = h;
                g_zl[o] = l;
            }
        }
        const int FT = Pc * Fc * Kc * Gc;
        int tot = 2048 * 256;
        int gid = sbid * 256 + tid;
        for (int i = gid; i < FT; i += tot) {
            __nv_bfloat16 h, l;
            split2(fw[i], h, l);
            g_fwh[i] = h;
            g_fwl[i] = l;
        }
    }
}

// ======================= 4. prop v5: bank-swizzled sparse propagation =========
// Same as v4, except zin is XOR-swizzled at float4 granularity:
//   chunk c of row i lives at position (c ^ (i & 7)) -> rows start in 8 bank
//   classes instead of all at bank 0, breaking the structural 4-way conflict
//   between the 4 jj-lanes reading random rows at the same gq banks.
#define PSTG_OFF (Nn * 32 * 4)         /* 131072 */
#define WSTG 1152
#define PSMEM (PSTG_OFF + 16 * WSTG)   /* 149504 */

__global__ void __launch_bounds__(512, 1)
prop_kernel(int ks) {
    extern __shared__ __align__(16) char psm[];
    float* zin = (float*)psm;
    const float2* stg = (const float2*)(psm + PSTG_OFF);
    uint32_t sb = smem_u32(psm);
    const int bp = blockIdx.y, b = bp >> 2, gb = blockIdx.x;
    const int tid = threadIdx.x, w = tid >> 5, lane = tid & 31;
    const int jj = lane >> 3, gq = lane & 7;
    const int soff = lane & 7;
    const size_t NN = (size_t)Nn * Nn;

    const float* src = g_zf + (size_t)bp * NN + (size_t)(ks - 1) * Gc + (size_t)gb * 32;
#pragma unroll
    for (int r = 0; r < 16; ++r) {
        int idx = r * 512 + tid;
        int row = idx >> 3, c4 = idx & 7;
        float4 v = *(const float4*)(src + (size_t)row * Nn + c4 * 4);
        *(float4*)(zin + row * 32 + ((c4 ^ (row & 7)) * 4)) = v;   // swizzled store
    }
    __syncthreads();

    const uint32_t stga = sb + PSTG_OFF + w * WSTG + jj * 144 + soff * 16;

    for (int jb = w * 4; jb < Nn; jb += 64) {
        int cj = g_cnt[b * Nn + jb + (lane & 3)];
        cj = max(cj, __shfl_xor_sync(0xffffffffu, cj, 1));
        cj = max(cj, __shfl_xor_sync(0xffffffffu, cj, 2));
        int nch = (cj + 15) >> 4;
        const float2* arow = g_avi + ((size_t)bp * Nn + jb + jj) * MAXS;

        cpa16(stga, arow + soff * 2);
        cpa_commit();
        float4 acc0 = make_float4(0.f, 0.f, 0.f, 0.f);
        float4 acc1 = make_float4(0.f, 0.f, 0.f, 0.f);
        for (int c = 0; c < nch; ++c) {
            if (c + 1 < nch) {
                cpa16(stga + ((c + 1) & 1) * 576, arow + (c + 1) * 16 + soff * 2);
                cpa_commit();
                cpa_wait1();
            } else {
                cpa_wait0();
            }
            __syncwarp();
            const float2* bufp = stg + (w * 144 + (c & 1) * 72 + jj * 18);
#pragma unroll
            for (int q = 0; q < 16; ++q) {
                float2 av = bufp[q];
                int i = __float_as_int(av.y);
                float a = av.x;
                const float4 zv = *(const float4*)(zin + i * 32 + ((gq ^ (i & 7)) * 4));  // swizzled load
                if (q & 1) {
                    acc1.x = fmaf(a, zv.x, acc1.x);
                    acc1.y = fmaf(a, zv.y, acc1.y);
                    acc1.z = fmaf(a, zv.z, acc1.z);
                    acc1.w = fmaf(a, zv.w, acc1.w);
                } else {
                    acc0.x = fmaf(a, zv.x, acc0.x);
                    acc0.y = fmaf(a, zv.y, acc0.y);
                    acc0.z = fmaf(a, zv.z, acc0.z);
                    acc0.w = fmaf(a, zv.w, acc0.w);
                }
            }
            __syncwarp();
        }
        float4 acc = make_float4(acc0.x + acc1.x, acc0.y + acc1.y,
                                 acc0.z + acc1.z, acc0.w + acc1.w);
        int j = jb + jj;
        size_t o = ((size_t)bp * Nn + j) * Nn + (size_t)ks * Gc + gb * 32 + gq * 4;
        *(float4*)(g_zf + o) = acc;
        __nv_bfloat16 h0, l0, h1, l1, h2, l2, h3, l3;
        split2(acc.x, h0, l0);
        split2(acc.y, h1, l1);
        split2(acc.z, h2, l2);
        split2(acc.w, h3, l3);
        __nv_bfloat162 ph01, ph23, pl01, pl23;
        ph01.x = h0; ph01.y = h1; ph23.x = h2; ph23.y = h3;
        pl01.x = l0; pl01.y = l1; pl23.x = l2; pl23.y = l3;
        *(__nv_bfloat162*)(g_zh + o) = ph01;
        *(__nv_bfloat162*)(g_zh + o + 2) = ph23;
        *(__nv_bfloat162*)(g_zl + o) = pl01;
        *(__nv_bfloat162*)(g_zl + o + 2) = pl23;
    }
}

// ======================= 5. HMMA filter GEMM ===================================
#define TBK 32
#define NCH (Nn / TBK)
#define ASTG 16384
#define BSTG 16384
#define STG (ASTG + BSTG)
#define NSTAGE 3
#define SMEM_GEMM (NSTAGE * STG)

__global__ void __launch_bounds__(256, 2)
mma_gemm(const float* __restrict__ bias, float* __restrict__ out) {
    extern __shared__ __align__(1024) char smem[];
    uint32_t sb = smem_u32(smem);
    const int bp = blockIdx.z, p = bp & 3;
    const int m0 = blockIdx.y * 128, n0 = blockIdx.x * 128;
    const int tid = threadIdx.x, wid = tid >> 5, lane = tid & 31;
    const int warp_m = wid >> 2, warp_n = wid & 3;
    const size_t NN = (size_t)Nn * Nn;

    const __nv_bfloat16* Ah = g_fwh + (size_t)p * Fc * Nn;
    const __nv_bfloat16* Al = g_fwl + (size_t)p * Fc * Nn;
    const __nv_bfloat16* Bh = g_zh + (size_t)bp * NN;
    const __nv_bfloat16* Bl = g_zl + (size_t)bp * NN;

    float acc[4][4][4];
#pragma unroll
    for (int i = 0; i < 4; ++i)
#pragma unroll
        for (int j = 0; j < 4; ++j)
#pragma unroll
            for (int q = 0; q < 4; ++q) acc[i][j][q] = 0.f;

    auto load_stage = [&](int c, int s) {
        uint32_t base = sb + s * STG;
        int k0 = c * TBK;
#pragma unroll
        for (int i = 0; i < 4; ++i) {
            int idx = i * 256 + tid;
            int r = idx >> 3, ch = idx & 7;
            const __nv_bfloat16* srcp = ((ch < 4) ? Ah : Al) + (size_t)(m0 + r) * Nn + k0 + (ch & 3) * 8;
            cpa16(base + SWZ(r * 128 + ch * 16), srcp);
        }
#pragma unroll
        for (int i = 0; i < 4; ++i) {
            int idx = i * 256 + tid;
            int r = idx >> 3, ch = idx & 7;
            const __nv_bfloat16* srcp = ((ch < 4) ? Bh : Bl) + (size_t)(n0 + r) * Nn + k0 + (ch & 3) * 8;
            cpa16(base + ASTG + SWZ(r * 128 + ch * 16), srcp);
        }
        cpa_commit();
    };

    const int a_row = (lane & 7) + ((lane >> 3) & 1) * 8;
    const int a_k16 = lane >> 4;
    const int b_row = (lane & 7);
    const int b_par = (lane >> 3) & 1;

    load_stage(0, 0);
    load_stage(1, 1);
    for (int c = 0; c < NCH; ++c) {
        if (c + 2 < NCH) {
            load_stage(c + 2, (c + 2) % NSTAGE);
            cpa_wait2();
        } else if (c + 1 < NCH) {
            cpa_wait1();
        } else {
            cpa_wait0();
        }
        __syncthreads();
        uint32_t Abase = sb + (c % NSTAGE) * STG;
        uint32_t Bbase = Abase + ASTG;
#pragma unroll
        for (int s = 0; s < 2; ++s) {
            uint32_t bh2[4][2], bl2[4][2];
#pragma unroll
            for (int o = 0; o < 4; ++o) {
                int row = warp_n * 32 + o * 8 + b_row;
                int chk = s * 2 + b_par;
                ldm_x2(bh2[o][0], bh2[o][1], Bbase + SWZ(row * 128 + chk * 16));
                ldm_x2(bl2[o][0], bl2[o][1], Bbase + SWZ(row * 128 + 64 + chk * 16));
            }
            uint32_t ah[4][4], al[4][4];
#pragma unroll
            for (int mt = 0; mt < 4; ++mt) {
                int row = warp_m * 64 + mt * 16 + a_row;
                int chh = s * 2 + a_k16;
                ldm_x4(ah[mt][0], ah[mt][1], ah[mt][2], ah[mt][3],
                       Abase + SWZ(row * 128 + chh * 16));
                ldm_x4(al[mt][0], al[mt][1], al[mt][2], al[mt][3],
                       Abase + SWZ(row * 128 + 64 + chh * 16));
            }
#pragma unroll
            for (int mt = 0; mt < 4; ++mt)
#pragma unroll
                for (int o = 0; o < 4; ++o) mma16816(acc[mt][o], ah[mt], bh2[o]);
#pragma unroll
            for (int mt = 0; mt < 4; ++mt)
#pragma unroll
                for (int o = 0; o < 4; ++o) mma16816(acc[mt][o], ah[mt], bl2[o]);
#pragma unroll
            for (int mt = 0; mt < 4; ++mt)
#pragma unroll
                for (int o = 0; o < 4; ++o) mma16816(acc[mt][o], al[mt], bh2[o]);
        }
        __syncthreads();
    }

    float* C = out + (size_t)bp * Fc * Nn;
    const int r_base = m0 + warp_m * 64 + (lane >> 2);
    const int c_base = n0 + warp_n * 32 + (lane & 3) * 2;
#pragma unroll
    for (int mt = 0; mt < 4; ++mt)
#pragma unroll
        for (int o = 0; o < 4; ++o) {
#pragma unroll
            for (int h = 0; h < 2; ++h) {
                int r = r_base + mt * 16 + h * 8;
                int cc = c_base + o * 8;
                float bv = bias[r];
                float t0 = acc[mt][o][2 * h] + bv;
                float t1 = acc[mt][o][2 * h + 1] + bv;
                t0 = t0 > 0.f ? t0 : 0.01f * t0;
                t1 = t1 > 0.f ? t1 : 0.01f * t1;
                *(float2*)(C + (size_t)r * Nn + cc) = make_float2(t0, t1);
            }
        }
}

// ======================= launch ================================================
extern "C" void kernel_launch(void* const* d_in, const int* in_sizes, int n_in,
                              void* d_out, int out_size) {
    const float* x      = (const float*)d_in[0];
    const float* mixer  = (const float*)d_in[1];
    const float* weight = (const float*)d_in[2];
    const float* wb     = (const float*)d_in[3];
    const float* fw     = (const float*)d_in[4];
    const float* bias   = (const float*)d_in[5];
    const float* S      = (const float*)d_in[6];
    float* out = (float*)d_out;

    cudaFuncSetAttribute(mma_gemm, cudaFuncAttributeMaxDynamicSharedMemorySize, SMEM_GEMM);
    cudaFuncSetAttribute(prop_kernel, cudaFuncAttributeMaxDynamicSharedMemorySize, PSMEM);

    peidx_kernel<<<1152, 256>>>(x, mixer, weight, wb, S);      // 1
    ms_kernel<<<dim3(Nn, NBP), 256>>>(S);                      // 2
    fillsplit_kernel<<<6144, 256>>>(x, fw);                    // 3
    for (int k = 1; k < Kc; ++k)                               // 4 (profiled), 5, 6
        prop_kernel<<<dim3(8, NBP), 512, PSMEM>>>(k);
    mma_gemm<<<dim3(Nn / 128, Fc / 128, NBP), 256, SMEM_GEMM>>>(bias, out);  // 7
}

// round 13
// speedup vs baseline: 1.0191x; 1.0191x over previous
#include <cuda_runtime.h>
#include <cuda_bf16.h>
#include <cstdint>

#define Bc 8
#define Gc 256
#define Nn 1024
#define Pc 4
#define Fc 256
#define Kc 4
#define NBP 32
#define MAXS 128

// ======================= device scratch ======================================
__device__ float g_e1[NBP * Nn];
__device__ float g_e2[NBP * Nn];
__device__ float g_m[NBP * Nn];
__device__ float g_s[NBP * Nn];
__device__ int g_cnt[Bc * Nn];
__device__ unsigned short g_idx[(size_t)Bc * Nn * MAXS];    // 2 MB
__device__ float2 g_avi[(size_t)NBP * Nn * MAXS];           // 32 MB (value, i-bits), zero-padded
__device__ float g_zf[(size_t)NBP * Nn * Nn];               // 128 MB zT fp32 [bp][n][kG]
__device__ __nv_bfloat16 g_zh[(size_t)NBP * Nn * Nn];       // 64 MB zT hi
__device__ __nv_bfloat16 g_zl[(size_t)NBP * Nn * Nn];       // 64 MB zT lo
__device__ __nv_bfloat16 g_fwh[(size_t)Pc * Fc * Kc * Gc];
__device__ __nv_bfloat16 g_fwl[(size_t)Pc * Fc * Kc * Gc];

__device__ __forceinline__ void split2(float v, __nv_bfloat16& h, __nv_bfloat16& l) {
    h = __float2bfloat16(v);
    l = __float2bfloat16(v - __bfloat162float(h));
}

// ======================= helpers =============================================
__device__ __forceinline__ uint32_t smem_u32(const void* p) {
    uint32_t a;
    asm("{ .reg .u64 t; cvta.to.shared.u64 t, %1; cvt.u32.u64 %0, t; }" : "=r"(a) : "l"(p));
    return a;
}
__device__ __forceinline__ void cpa16(uint32_t dst, const void* src) {
    asm volatile("cp.async.cg.shared.global [%0], [%1], 16;" :: "r"(dst), "l"(src));
}
__device__ __forceinline__ void cpa_commit() { asm volatile("cp.async.commit_group;" ::: "memory"); }
__device__ __forceinline__ void cpa_wait2() { asm volatile("cp.async.wait_group 2;" ::: "memory"); }
__device__ __forceinline__ void cpa_wait1() { asm volatile("cp.async.wait_group 1;" ::: "memory"); }
__device__ __forceinline__ void cpa_wait0() { asm volatile("cp.async.wait_group 0;" ::: "memory"); }

#define SWZ(off) ((off) ^ (((off) >> 3) & 0x70))

__device__ __forceinline__ void ldm_x4(uint32_t& r0, uint32_t& r1, uint32_t& r2, uint32_t& r3,
                                       uint32_t addr) {
    asm volatile("ldmatrix.sync.aligned.m8n8.x4.shared.b16 {%0,%1,%2,%3}, [%4];"
                 : "=r"(r0), "=r"(r1), "=r"(r2), "=r"(r3) : "r"(addr));
}
__device__ __forceinline__ void ldm_x2(uint32_t& r0, uint32_t& r1, uint32_t addr) {
    asm volatile("ldmatrix.sync.aligned.m8n8.x2.shared.b16 {%0,%1}, [%2];"
                 : "=r"(r0), "=r"(r1) : "r"(addr));
}
__device__ __forceinline__ void mma16816(float* c, const uint32_t* a, const uint32_t* b) {
    asm volatile(
        "mma.sync.aligned.m16n8k16.row.col.f32.bf16.bf16.f32 "
        "{%0,%1,%2,%3}, {%4,%5,%6,%7}, {%8,%9}, {%0,%1,%2,%3};"
        : "+f"(c[0]), "+f"(c[1]), "+f"(c[2]), "+f"(c[3])
        : "r"(a[0]), "r"(a[1]), "r"(a[2]), "r"(a[3]), "r"(b[0]), "r"(b[1]));
}

// ======================= reductions ==========================================
__device__ __forceinline__ float blockReduceMax(float v, float* sm) {
#pragma unroll
    for (int o = 16; o; o >>= 1) v = fmaxf(v, __shfl_xor_sync(0xffffffffu, v, o));
    if ((threadIdx.x & 31) == 0) sm[threadIdx.x >> 5] = v;
    __syncthreads();
    if (threadIdx.x < 32) {
        float t = (threadIdx.x < 8) ? sm[threadIdx.x] : -3.0e38f;
#pragma unroll
        for (int o = 4; o; o >>= 1) t = fmaxf(t, __shfl_xor_sync(0xffffffffu, t, o));
        if (threadIdx.x == 0) sm[0] = t;
    }
    __syncthreads();
    float r = sm[0];
    __syncthreads();
    return r;
}
__device__ __forceinline__ float blockReduceSum(float v, float* sm) {
#pragma unroll
    for (int o = 16; o; o >>= 1) v += __shfl_xor_sync(0xffffffffu, v, o);
    if ((threadIdx.x & 31) == 0) sm[threadIdx.x >> 5] = v;
    __syncthreads();
    if (threadIdx.x < 32) {
        float t = (threadIdx.x < 8) ? sm[threadIdx.x] : 0.f;
#pragma unroll
        for (int o = 4; o; o >>= 1) t += __shfl_xor_sync(0xffffffffu, t, o);
        if (threadIdx.x == 0) sm[0] = t;
    }
    __syncthreads();
    float r = sm[0];
    __syncthreads();
    return r;
}

// ======================= 1. fused pe + idxT ====================================
// bid < 128: pe block (bp = bid>>2, n-block = bid&3)
// bid >= 128: transpose-tile CSC build: fb = bid-128 in [0,256): b = fb>>5,
//   j-group = (fb&31)*32. Coalesced 32x32 tile loads; per-column sequential
//   compaction preserves ascending-i order (deterministic, same as before).
__global__ void peidx_kernel(const float* __restrict__ x,
                             const float* __restrict__ mixer,
                             const float* __restrict__ weight,
                             const float* __restrict__ wb,
                             const float* __restrict__ S) {
    __shared__ __align__(16) char sbuf[4352];   // tile 32x33 floats (4224) or pe s1/s2/sc
    __shared__ int ccnt[32];
    int bid = blockIdx.x, tid = threadIdx.x;
    if (bid < 128) {
        int bp = bid >> 2;
        int b = bp >> 2, p = bp & 3;
        float* s1 = (float*)sbuf;
        float* s2 = s1 + Gc;
        float* sc = (float*)ccnt;   // reuse ccnt space for the two constants
        {
            int g = tid;
            float v1 = 0.f, v2 = 0.f;
            const float* mw1 = mixer + p * 2 * Fc;
            const float* mw2 = mw1 + Fc;
#pragma unroll 8
            for (int f = 0; f < Fc; ++f) {
                float w = weight[((size_t)(p * Fc + f)) * Gc + g];
                v1 = fmaf(mw1[f], w, v1);
                v2 = fmaf(mw2[f], w, v2);
            }
            s1[g] = v1;
            s2[g] = v2;
            if (g == 0) {
                float c1 = 0.f, c2 = 0.f;
                for (int f = 0; f < Fc; ++f) {
                    c1 = fmaf(mw1[f], wb[p * Fc + f], c1);
                    c2 = fmaf(mw2[f], wb[p * Fc + f], c2);
                }
                sc[0] = c1;
                sc[1] = c2;
            }
        }
        __syncthreads();
        int n = (bid & 3) * 256 + tid;
        const float* xb = x + (size_t)b * Gc * Nn + n;
        float a1 = 0.f, a2 = 0.f;
#pragma unroll 8
        for (int g = 0; g < Gc; ++g) {
            float xv = xb[(size_t)g * Nn];
            a1 = fmaf(s1[g], xv, a1);
            a2 = fmaf(s2[g], xv, a2);
        }
        g_e1[bp * Nn + n] = a1 + sc[0];
        g_e2[bp * Nn + n] = a2 + sc[1];
    } else {
        int fb = bid - 128;
        int b = fb >> 5;
        int j0 = (fb & 31) * 32;
        float(*tile)[33] = (float(*)[33])sbuf;
        int tx = tid & 31, ty = tid >> 5;   // ty 0..7
        if (tid < 32) ccnt[tid] = 0;
        __syncthreads();
        const float* Sb = S + (size_t)b * Nn * Nn;
        for (int it = 0; it < 32; ++it) {
            int i0 = it * 32;
#pragma unroll
            for (int q = 0; q < 4; ++q) {
                int r = ty + q * 8;
                tile[r][tx] = Sb[(size_t)(i0 + r) * Nn + j0 + tx];
            }
            __syncthreads();
            if (tid < 32) {
                int j = j0 + tid;
                int c = ccnt[tid];
                unsigned short* ip = g_idx + ((size_t)b * Nn + j) * MAXS;
#pragma unroll 8
                for (int r = 0; r < 32; ++r) {
                    if (fabsf(tile[r][tid]) > 1e-9f) {
                        if (c < MAXS) ip[c] = (unsigned short)(i0 + r);
                        ++c;
                    }
                }
                ccnt[tid] = c;
            }
            __syncthreads();
        }
        if (tid < 32) g_cnt[b * Nn + j0 + tid] = ccnt[tid] < MAXS ? ccnt[tid] : MAXS;
    }
}

// ======================= 2. ms: per-row softmax stats, all 4 p per block ======
__global__ void ms_kernel(const float* __restrict__ S) {
    int i = blockIdx.x, b = blockIdx.y;
    __shared__ float sm[8];
    const float* Sr = S + ((size_t)b * Nn + i) * Nn;
    int mk[4];
    float lv[4][4];   // [p][q]
    float e2i[4];
#pragma unroll
    for (int p = 0; p < 4; ++p) e2i[p] = g_e2[(b * 4 + p) * Nn + i];
#pragma unroll
    for (int q = 0; q < 4; ++q) {
        int j = threadIdx.x + q * 256;
        mk[q] = (fabsf(Sr[j]) > 1e-9f);
#pragma unroll
        for (int p = 0; p < 4; ++p) {
            float e = g_e1[(b * 4 + p) * Nn + j] + e2i[p];
            lv[p][q] = e > 0.f ? e : 0.2f * e;
        }
    }
#pragma unroll
    for (int p = 0; p < 4; ++p) {
        float vmax = -3.0e38f;
#pragma unroll
        for (int q = 0; q < 4; ++q)
            if (mk[q]) vmax = fmaxf(vmax, lv[p][q]);
        vmax = blockReduceMax(vmax, sm);
        float sum = 0.f;
#pragma unroll
        for (int q = 0; q < 4; ++q)
            sum += mk[q] ? __expf(lv[p][q] - vmax) : 0.f;
        sum = blockReduceSum(sum, sm);
        if (threadIdx.x == 0) {
            g_m[(b * 4 + p) * Nn + i] = vmax;
            g_s[(b * 4 + p) * Nn + i] = sum;
        }
    }
}

// ======================= 3. fused fill + split =================================
__global__ void fillsplit_kernel(const float* __restrict__ x, const float* __restrict__ fw) {
    __shared__ float t[32][33];
    int bid = blockIdx.x, tid = threadIdx.x;
    if (bid < 4096) {
        int bp = bid >> 7, b = bp >> 2;
        int w = tid >> 5, lane = tid & 31;
        int j = (bid & 127) * 8 + w;
        int cnt = g_cnt[b * Nn + j];
        float e1j = g_e1[bp * Nn + j];
        const unsigned short* ip = g_idx + ((size_t)b * Nn + j) * MAXS;
        float2* ap = g_avi + ((size_t)bp * Nn + j) * MAXS;
#pragma unroll
        for (int s = lane; s < MAXS; s += 32) {
            float2 o = make_float2(0.f, __int_as_float(0));
            if (s < cnt) {
                int i = ip[s];
                float e = e1j + g_e2[bp * Nn + i];
                float l = e > 0.f ? e : 0.2f * e;
                o = make_float2(__expf(l - g_m[bp * Nn + i]) / g_s[bp * Nn + i], __int_as_float(i));
            }
            ap[s] = o;
        }
    } else {
        int sbid = bid - 4096;
        int b = sbid >> 8;
        int g0 = ((sbid >> 5) & 7) * 32, n0 = (sbid & 31) * 32;
        int tx = tid & 31, ty = tid >> 5;
        const float* xp = x + ((size_t)b * Gc + g0) * Nn + n0;
#pragma unroll
        for (int q = 0; q < 4; ++q) {
            int g = ty + q * 8;
            t[g][tx] = xp[(size_t)g * Nn + tx];
        }
        __syncthreads();
#pragma unroll
        for (int q = 0; q < 4; ++q) {
            int nn = ty + q * 8;
            float v = t[tx][nn];
            __nv_bfloat16 h, l;
            split2(v, h, l);
#pragma unroll
            for (int p = 0; p < 4; ++p) {
                size_t o = (((size_t)(b * 4 + p) * Nn) + n0 + nn) * Nn + g0 + tx;
                g_zf[o] = v;
                g_zh[o] = h;
                g_zl[o] = l;
            }
        }
        const int FT = Pc * Fc * Kc * Gc;
        int tot = 2048 * 256;
        int gid = sbid * 256 + tid;
        for (int i = gid; i < FT; i += tot) {
            __nv_bfloat16 h, l;
            split2(fw[i], h, l);
            g_fwh[i] = h;
            g_fwl[i] = l;
        }
    }
}

// ======================= 4. prop (R11 version, no swizzle) =====================
#define PSTG_OFF (Nn * 32 * 4)         /* 131072 */
#define WSTG 1152
#define PSMEM (PSTG_OFF + 16 * WSTG)   /* 149504 */

__global__ void __launch_bounds__(512, 1)
prop_kernel(int ks) {
    extern __shared__ __align__(16) char psm[];
    float* zin = (float*)psm;
    const float2* stg = (const float2*)(psm + PSTG_OFF);
    uint32_t sb = smem_u32(psm);
    const int bp = blockIdx.y, b = bp >> 2, gb = blockIdx.x;
    const int tid = threadIdx.x, w = tid >> 5, lane = tid & 31;
    const int jj = lane >> 3, gq = lane & 7;
    const int soff = lane & 7;
    const size_t NN = (size_t)Nn * Nn;

    const float* src = g_zf + (size_t)bp * NN + (size_t)(ks - 1) * Gc + (size_t)gb * 32;
#pragma unroll
    for (int r = 0; r < 16; ++r) {
        int idx = r * 512 + tid;
        int row = idx >> 3, c4 = idx & 7;
        float4 v = *(const float4*)(src + (size_t)row * Nn + c4 * 4);
        *(float4*)(zin + row * 32 + c4 * 4) = v;
    }
    __syncthreads();

    const uint32_t stga = sb + PSTG_OFF + w * WSTG + jj * 144 + soff * 16;

    for (int jb = w * 4; jb < Nn; jb += 64) {
        int cj = g_cnt[b * Nn + jb + (lane & 3)];
        cj = max(cj, __shfl_xor_sync(0xffffffffu, cj, 1));
        cj = max(cj, __shfl_xor_sync(0xffffffffu, cj, 2));
        int nch = (cj + 15) >> 4;
        const float2* arow = g_avi + ((size_t)bp * Nn + jb + jj) * MAXS;

        cpa16(stga, arow + soff * 2);
        cpa_commit();
        float4 acc0 = make_float4(0.f, 0.f, 0.f, 0.f);
        float4 acc1 = make_float4(0.f, 0.f, 0.f, 0.f);
        for (int c = 0; c < nch; ++c) {
            if (c + 1 < nch) {
                cpa16(stga + ((c + 1) & 1) * 576, arow + (c + 1) * 16 + soff * 2);
                cpa_commit();
                cpa_wait1();
            } else {
                cpa_wait0();
            }
            __syncwarp();
            const float2* bufp = stg + (w * 144 + (c & 1) * 72 + jj * 18);
#pragma unroll
            for (int q = 0; q < 16; ++q) {
                float2 av = bufp[q];
                int i = __float_as_int(av.y);
                float a = av.x;
                const float4 zv = *(const float4*)(zin + i * 32 + gq * 4);
                if (q & 1) {
                    acc1.x = fmaf(a, zv.x, acc1.x);
                    acc1.y = fmaf(a, zv.y, acc1.y);
                    acc1.z = fmaf(a, zv.z, acc1.z);
                    acc1.w = fmaf(a, zv.w, acc1.w);
                } else {
                    acc0.x = fmaf(a, zv.x, acc0.x);
                    acc0.y = fmaf(a, zv.y, acc0.y);
                    acc0.z = fmaf(a, zv.z, acc0.z);
                    acc0.w = fmaf(a, zv.w, acc0.w);
                }
            }
            __syncwarp();
        }
        float4 acc = make_float4(acc0.x + acc1.x, acc0.y + acc1.y,
                                 acc0.z + acc1.z, acc0.w + acc1.w);
        int j = jb + jj;
        size_t o = ((size_t)bp * Nn + j) * Nn + (size_t)ks * Gc + gb * 32 + gq * 4;
        *(float4*)(g_zf + o) = acc;
        __nv_bfloat16 h0, l0, h1, l1, h2, l2, h3, l3;
        split2(acc.x, h0, l0);
        split2(acc.y, h1, l1);
        split2(acc.z, h2, l2);
        split2(acc.w, h3, l3);
        __nv_bfloat162 ph01, ph23, pl01, pl23;
        ph01.x = h0; ph01.y = h1; ph23.x = h2; ph23.y = h3;
        pl01.x = l0; pl01.y = l1; pl23.x = l2; pl23.y = l3;
        *(__nv_bfloat162*)(g_zh + o) = ph01;
        *(__nv_bfloat162*)(g_zh + o + 2) = ph23;
        *(__nv_bfloat162*)(g_zl + o) = pl01;
        *(__nv_bfloat162*)(g_zl + o + 2) = pl23;
    }
}

// ======================= 5. HMMA filter GEMM ===================================
#define TBK 32
#define NCH (Nn / TBK)
#define ASTG 16384
#define BSTG 16384
#define STG (ASTG + BSTG)
#define NSTAGE 3
#define SMEM_GEMM (NSTAGE * STG)

__global__ void __launch_bounds__(256, 2)
mma_gemm(const float* __restrict__ bias, float* __restrict__ out) {
    extern __shared__ __align__(1024) char smem[];
    uint32_t sb = smem_u32(smem);
    const int bp = blockIdx.z, p = bp & 3;
    const int m0 = blockIdx.y * 128, n0 = blockIdx.x * 128;
    const int tid = threadIdx.x, wid = tid >> 5, lane = tid & 31;
    const int warp_m = wid >> 2, warp_n = wid & 3;
    const size_t NN = (size_t)Nn * Nn;

    const __nv_bfloat16* Ah = g_fwh + (size_t)p * Fc * Nn;
    const __nv_bfloat16* Al = g_fwl + (size_t)p * Fc * Nn;
    const __nv_bfloat16* Bh = g_zh + (size_t)bp * NN;
    const __nv_bfloat16* Bl = g_zl + (size_t)bp * NN;

    float acc[4][4][4];
#pragma unroll
    for (int i = 0; i < 4; ++i)
#pragma unroll
        for (int j = 0; j < 4; ++j)
#pragma unroll
            for (int q = 0; q < 4; ++q) acc[i][j][q] = 0.f;

    auto load_stage = [&](int c, int s) {
        uint32_t base = sb + s * STG;
        int k0 = c * TBK;
#pragma unroll
        for (int i = 0; i < 4; ++i) {
            int idx = i * 256 + tid;
            int r = idx >> 3, ch = idx & 7;
            const __nv_bfloat16* srcp = ((ch < 4) ? Ah : Al) + (size_t)(m0 + r) * Nn + k0 + (ch & 3) * 8;
            cpa16(base + SWZ(r * 128 + ch * 16), srcp);
        }
#pragma unroll
        for (int i = 0; i < 4; ++i) {
            int idx = i * 256 + tid;
            int r = idx >> 3, ch = idx & 7;
            const __nv_bfloat16* srcp = ((ch < 4) ? Bh : Bl) + (size_t)(n0 + r) * Nn + k0 + (ch & 3) * 8;
            cpa16(base + ASTG + SWZ(r * 128 + ch * 16), srcp);
        }
        cpa_commit();
    };

    const int a_row = (lane & 7) + ((lane >> 3) & 1) * 8;
    const int a_k16 = lane >> 4;
    const int b_row = (lane & 7);
    const int b_par = (lane >> 3) & 1;

    load_stage(0, 0);
    load_stage(1, 1);
    for (int c = 0; c < NCH; ++c) {
        if (c + 2 < NCH) {
            load_stage(c + 2, (c + 2) % NSTAGE);
            cpa_wait2();
        } else if (c + 1 < NCH) {
            cpa_wait1();
        } else {
            cpa_wait0();
        }
        __syncthreads();
        uint32_t Abase = sb + (c % NSTAGE) * STG;
        uint32_t Bbase = Abase + ASTG;
#pragma unroll
        for (int s = 0; s < 2; ++s) {
            uint32_t bh2[4][2], bl2[4][2];
#pragma unroll
            for (int o = 0; o < 4; ++o) {
                int row = warp_n * 32 + o * 8 + b_row;
                int chk = s * 2 + b_par;
                ldm_x2(bh2[o][0], bh2[o][1], Bbase + SWZ(row * 128 + chk * 16));
                ldm_x2(bl2[o][0], bl2[o][1], Bbase + SWZ(row * 128 + 64 + chk * 16));
            }
            uint32_t ah[4][4], al[4][4];
#pragma unroll
            for (int mt = 0; mt < 4; ++mt) {
                int row = warp_m * 64 + mt * 16 + a_row;
                int chh = s * 2 + a_k16;
                ldm_x4(ah[mt][0], ah[mt][1], ah[mt][2], ah[mt][3],
                       Abase + SWZ(row * 128 + chh * 16));
                ldm_x4(al[mt][0], al[mt][1], al[mt][2], al[mt][3],
                       Abase + SWZ(row * 128 + 64 + chh * 16));
            }
#pragma unroll
            for (int mt = 0; mt < 4; ++mt)
#pragma unroll
                for (int o = 0; o < 4; ++o) mma16816(acc[mt][o], ah[mt], bh2[o]);
#pragma unroll
            for (int mt = 0; mt < 4; ++mt)
#pragma unroll
                for (int o = 0; o < 4; ++o) mma16816(acc[mt][o], ah[mt], bl2[o]);
#pragma unroll
            for (int mt = 0; mt < 4; ++mt)
#pragma unroll
                for (int o = 0; o < 4; ++o) mma16816(acc[mt][o], al[mt], bh2[o]);
        }
        __syncthreads();
    }

    float* C = out + (size_t)bp * Fc * Nn;
    const int r_base = m0 + warp_m * 64 + (lane >> 2);
    const int c_base = n0 + warp_n * 32 + (lane & 3) * 2;
#pragma unroll
    for (int mt = 0; mt < 4; ++mt)
#pragma unroll
        for (int o = 0; o < 4; ++o) {
#pragma unroll
            for (int h = 0; h < 2; ++h) {
                int r = r_base + mt * 16 + h * 8;
                int cc = c_base + o * 8;
                float bv = bias[r];
                float t0 = acc[mt][o][2 * h] + bv;
                float t1 = acc[mt][o][2 * h + 1] + bv;
                t0 = t0 > 0.f ? t0 : 0.01f * t0;
                t1 = t1 > 0.f ? t1 : 0.01f * t1;
                *(float2*)(C + (size_t)r * Nn + cc) = make_float2(t0, t1);
            }
        }
}

// ======================= launch ================================================
extern "C" void kernel_launch(void* const* d_in, const int* in_sizes, int n_in,
                              void* d_out, int out_size) {
    const float* x      = (const float*)d_in[0];
    const float* mixer  = (const float*)d_in[1];
    const float* weight = (const float*)d_in[2];
    const float* wb     = (const float*)d_in[3];
    const float* fw     = (const float*)d_in[4];
    const float* bias   = (const float*)d_in[5];
    const float* S      = (const float*)d_in[6];
    float* out = (float*)d_out;

    cudaFuncSetAttribute(mma_gemm, cudaFuncAttributeMaxDynamicSharedMemorySize, SMEM_GEMM);
    cudaFuncSetAttribute(prop_kernel, cudaFuncAttributeMaxDynamicSharedMemorySize, PSMEM);

    peidx_kernel<<<384, 256>>>(x, mixer, weight, wb, S);       // 1 (pe 128 + idxT 256)
    ms_kernel<<<dim3(Nn, Bc), 256>>>(S);                       // 2 (4 p per block)
    fillsplit_kernel<<<6144, 256>>>(x, fw);                    // 3
    for (int k = 1; k < Kc; ++k)                               // 4 (profiled), 5, 6
        prop_kernel<<<dim3(8, NBP), 512, PSMEM>>>(k);
    mma_gemm<<<dim3(Nn / 128, Fc / 128, NBP), 256, SMEM_GEMM>>>(bias, out);  // 7
}

// round 15
// speedup vs baseline: 1.0328x; 1.0135x over previous
#include <cuda_runtime.h>
#include <cuda_bf16.h>
#include <cstdint>

#define Bc 8
#define Gc 256
#define Nn 1024
#define Pc 4
#define Fc 256
#define Kc 4
#define NBP 32
#define MAXS 128

// ======================= device scratch ======================================
__device__ float g_e1[NBP * Nn];
__device__ float g_e2[NBP * Nn];
__device__ float g_m[NBP * Nn];
__device__ float g_s[NBP * Nn];
__device__ int g_cnt[Bc * Nn];
__device__ unsigned short g_idx[(size_t)Bc * Nn * MAXS];    // 2 MB
__device__ unsigned short g_jord[Bc * Nn];                  // cnt-sorted column order
__device__ float2 g_avi[(size_t)NBP * Nn * MAXS];           // 32 MB (value, i-bits), zero-padded
__device__ float g_zf[(size_t)NBP * Nn * Nn];               // 128 MB zT fp32 [bp][n][kG]
__device__ __nv_bfloat16 g_zh[(size_t)NBP * Nn * Nn];       // 64 MB zT hi
__device__ __nv_bfloat16 g_zl[(size_t)NBP * Nn * Nn];       // 64 MB zT lo
__device__ __nv_bfloat16 g_fwh[(size_t)Pc * Fc * Kc * Gc];
__device__ __nv_bfloat16 g_fwl[(size_t)Pc * Fc * Kc * Gc];

__device__ __forceinline__ void split2(float v, __nv_bfloat16& h, __nv_bfloat16& l) {
    h = __float2bfloat16(v);
    l = __float2bfloat16(v - __bfloat162float(h));
}

// ======================= helpers =============================================
__device__ __forceinline__ uint32_t smem_u32(const void* p) {
    uint32_t a;
    asm("{ .reg .u64 t; cvta.to.shared.u64 t, %1; cvt.u32.u64 %0, t; }" : "=r"(a) : "l"(p));
    return a;
}
__device__ __forceinline__ void cpa16(uint32_t dst, const void* src) {
    asm volatile("cp.async.cg.shared.global [%0], [%1], 16;" :: "r"(dst), "l"(src));
}
__device__ __forceinline__ void cpa_commit() { asm volatile("cp.async.commit_group;" ::: "memory"); }
__device__ __forceinline__ void cpa_wait2() { asm volatile("cp.async.wait_group 2;" ::: "memory"); }
__device__ __forceinline__ void cpa_wait1() { asm volatile("cp.async.wait_group 1;" ::: "memory"); }
__device__ __forceinline__ void cpa_wait0() { asm volatile("cp.async.wait_group 0;" ::: "memory"); }

#define SWZ(off) ((off) ^ (((off) >> 3) & 0x70))

__device__ __forceinline__ void ldm_x4(uint32_t& r0, uint32_t& r1, uint32_t& r2, uint32_t& r3,
                                       uint32_t addr) {
    asm volatile("ldmatrix.sync.aligned.m8n8.x4.shared.b16 {%0,%1,%2,%3}, [%4];"
                 : "=r"(r0), "=r"(r1), "=r"(r2), "=r"(r3) : "r"(addr));
}
__device__ __forceinline__ void ldm_x2(uint32_t& r0, uint32_t& r1, uint32_t addr) {
    asm volatile("ldmatrix.sync.aligned.m8n8.x2.shared.b16 {%0,%1}, [%2];"
                 : "=r"(r0), "=r"(r1) : "r"(addr));
}
__device__ __forceinline__ void mma16816(float* c, const uint32_t* a, const uint32_t* b) {
    asm volatile(
        "mma.sync.aligned.m16n8k16.row.col.f32.bf16.bf16.f32 "
        "{%0,%1,%2,%3}, {%4,%5,%6,%7}, {%8,%9}, {%0,%1,%2,%3};"
        : "+f"(c[0]), "+f"(c[1]), "+f"(c[2]), "+f"(c[3])
        : "r"(a[0]), "r"(a[1]), "r"(a[2]), "r"(a[3]), "r"(b[0]), "r"(b[1]));
}

// ======================= reductions ==========================================
__device__ __forceinline__ float blockReduceMax(float v, float* sm) {
#pragma unroll
    for (int o = 16; o; o >>= 1) v = fmaxf(v, __shfl_xor_sync(0xffffffffu, v, o));
    if ((threadIdx.x & 31) == 0) sm[threadIdx.x >> 5] = v;
    __syncthreads();
    if (threadIdx.x < 32) {
        float t = (threadIdx.x < 8) ? sm[threadIdx.x] : -3.0e38f;
#pragma unroll
        for (int o = 4; o; o >>= 1) t = fmaxf(t, __shfl_xor_sync(0xffffffffu, t, o));
        if (threadIdx.x == 0) sm[0] = t;
    }
    __syncthreads();
    float r = sm[0];
    __syncthreads();
    return r;
}
__device__ __forceinline__ float blockReduceSum(float v, float* sm) {
#pragma unroll
    for (int o = 16; o; o >>= 1) v += __shfl_xor_sync(0xffffffffu, v, o);
    if ((threadIdx.x & 31) == 0) sm[threadIdx.x >> 5] = v;
    __syncthreads();
    if (threadIdx.x < 32) {
        float t = (threadIdx.x < 8) ? sm[threadIdx.x] : 0.f;
#pragma unroll
        for (int o = 4; o; o >>= 1) t += __shfl_xor_sync(0xffffffffu, t, o);
        if (threadIdx.x == 0) sm[0] = t;
    }
    __syncthreads();
    float r = sm[0];
    __syncthreads();
    return r;
}

// ======================= 1. fused pe + idxT ====================================
__global__ void peidx_kernel(const float* __restrict__ x,
                             const float* __restrict__ mixer,
                             const float* __restrict__ weight,
                             const float* __restrict__ wb,
                             const float* __restrict__ S) {
    __shared__ __align__(16) char sbuf[4352];
    __shared__ int ccnt[32];
    int bid = blockIdx.x, tid = threadIdx.x;
    if (bid < 128) {
        int bp = bid >> 2;
        int b = bp >> 2, p = bp & 3;
        float* s1 = (float*)sbuf;
        float* s2 = s1 + Gc;
        float* sc = (float*)ccnt;
        {
            int g = tid;
            float v1 = 0.f, v2 = 0.f;
            const float* mw1 = mixer + p * 2 * Fc;
            const float* mw2 = mw1 + Fc;
#pragma unroll 8
            for (int f = 0; f < Fc; ++f) {
                float w = weight[((size_t)(p * Fc + f)) * Gc + g];
                v1 = fmaf(mw1[f], w, v1);
                v2 = fmaf(mw2[f], w, v2);
            }
            s1[g] = v1;
            s2[g] = v2;
            if (g == 0) {
                float c1 = 0.f, c2 = 0.f;
                for (int f = 0; f < Fc; ++f) {
                    c1 = fmaf(mw1[f], wb[p * Fc + f], c1);
                    c2 = fmaf(mw2[f], wb[p * Fc + f], c2);
                }
                sc[0] = c1;
                sc[1] = c2;
            }
        }
        __syncthreads();
        int n = (bid & 3) * 256 + tid;
        const float* xb = x + (size_t)b * Gc * Nn + n;
        float a1 = 0.f, a2 = 0.f;
#pragma unroll 8
        for (int g = 0; g < Gc; ++g) {
            float xv = xb[(size_t)g * Nn];
            a1 = fmaf(s1[g], xv, a1);
            a2 = fmaf(s2[g], xv, a2);
        }
        g_e1[bp * Nn + n] = a1 + sc[0];
        g_e2[bp * Nn + n] = a2 + sc[1];
    } else {
        int fb = bid - 128;
        int b = fb >> 5;
        int j0 = (fb & 31) * 32;
        float(*tile)[33] = (float(*)[33])sbuf;
        int tx = tid & 31, ty = tid >> 5;
        if (tid < 32) ccnt[tid] = 0;
        __syncthreads();
        const float* Sb = S + (size_t)b * Nn * Nn;
        for (int it = 0; it < 32; ++it) {
            int i0 = it * 32;
#pragma unroll
            for (int q = 0; q < 4; ++q) {
                int r = ty + q * 8;
                tile[r][tx] = Sb[(size_t)(i0 + r) * Nn + j0 + tx];
            }
            __syncthreads();
            if (tid < 32) {
                int j = j0 + tid;
                int c = ccnt[tid];
                unsigned short* ip = g_idx + ((size_t)b * Nn + j) * MAXS;
#pragma unroll 8
                for (int r = 0; r < 32; ++r) {
                    if (fabsf(tile[r][tid]) > 1e-9f) {
                        if (c < MAXS) ip[c] = (unsigned short)(i0 + r);
                        ++c;
                    }
                }
                ccnt[tid] = c;
            }
            __syncthreads();
        }
        if (tid < 32) g_cnt[b * Nn + j0 + tid] = ccnt[tid] < MAXS ? ccnt[tid] : MAXS;
    }
}

// ======================= 2. ms: per-row softmax stats, all 4 p per block ======
__global__ void ms_kernel(const float* __restrict__ S) {
    int i = blockIdx.x, b = blockIdx.y;
    __shared__ float sm[8];
    const float* Sr = S + ((size_t)b * Nn + i) * Nn;
    int mk[4];
    float lv[4][4];
    float e2i[4];
#pragma unroll
    for (int p = 0; p < 4; ++p) e2i[p] = g_e2[(b * 4 + p) * Nn + i];
#pragma unroll
    for (int q = 0; q < 4; ++q) {
        int j = threadIdx.x + q * 256;
        mk[q] = (fabsf(Sr[j]) > 1e-9f);
#pragma unroll
        for (int p = 0; p < 4; ++p) {
            float e = g_e1[(b * 4 + p) * Nn + j] + e2i[p];
            lv[p][q] = e > 0.f ? e : 0.2f * e;
        }
    }
#pragma unroll
    for (int p = 0; p < 4; ++p) {
        float vmax = -3.0e38f;
#pragma unroll
        for (int q = 0; q < 4; ++q)
            if (mk[q]) vmax = fmaxf(vmax, lv[p][q]);
        vmax = blockReduceMax(vmax, sm);
        float sum = 0.f;
#pragma unroll
        for (int q = 0; q < 4; ++q)
            sum += mk[q] ? __expf(lv[p][q] - vmax) : 0.f;
        sum = blockReduceSum(sum, sm);
        if (threadIdx.x == 0) {
            g_m[(b * 4 + p) * Nn + i] = vmax;
            g_s[(b * 4 + p) * Nn + i] = sum;
        }
    }
}

// ======================= 3. fused fill + split + cnt-sort ======================
__global__ void fillsplit_kernel(const float* __restrict__ x, const float* __restrict__ fw) {
    __shared__ float t[32][33];
    __shared__ int hoff[129];
    int bid = blockIdx.x, tid = threadIdx.x;
    if (bid < 4096) {
        int bp = bid >> 7, b = bp >> 2;
        int w = tid >> 5, lane = tid & 31;
        int j = (bid & 127) * 8 + w;
        int cnt = g_cnt[b * Nn + j];
        float e1j = g_e1[bp * Nn + j];
        const unsigned short* ip = g_idx + ((size_t)b * Nn + j) * MAXS;
        float2* ap = g_avi + ((size_t)bp * Nn + j) * MAXS;
#pragma unroll
        for (int s = lane; s < MAXS; s += 32) {
            float2 o = make_float2(0.f, __int_as_float(0));
            if (s < cnt) {
                int i = ip[s];
                float e = e1j + g_e2[bp * Nn + i];
                float l = e > 0.f ? e : 0.2f * e;
                o = make_float2(__expf(l - g_m[bp * Nn + i]) / g_s[bp * Nn + i], __int_as_float(i));
            }
            ap[s] = o;
        }
    } else if (bid < 6144) {
        int sbid = bid - 4096;
        int b = sbid >> 8;
        int g0 = ((sbid >> 5) & 7) * 32, n0 = (sbid & 31) * 32;
        int tx = tid & 31, ty = tid >> 5;
        const float* xp = x + ((size_t)b * Gc + g0) * Nn + n0;
#pragma unroll
        for (int q = 0; q < 4; ++q) {
            int g = ty + q * 8;
            t[g][tx] = xp[(size_t)g * Nn + tx];
        }
        __syncthreads();
#pragma unroll
        for (int q = 0; q < 4; ++q) {
            int nn = ty + q * 8;
            float v = t[tx][nn];
            __nv_bfloat16 h, l;
            split2(v, h, l);
#pragma unroll
            for (int p = 0; p < 4; ++p) {
                size_t o = (((size_t)(b * 4 + p) * Nn) + n0 + nn) * Nn + g0 + tx;
                g_zf[o] = v;
                g_zh[o] = h;
                g_zl[o] = l;
            }
        }
        const int FT = Pc * Fc * Kc * Gc;
        int tot = 2048 * 256;
        int gid = sbid * 256 + tid;
        for (int i = gid; i < FT; i += tot) {
            __nv_bfloat16 h, l;
            split2(fw[i], h, l);
            g_fwh[i] = h;
            g_fwl[i] = l;
        }
    } else {
        // counting sort of columns by cnt (per b); bucket order arbitrary —
        // per-j math is independent, so results are bit-identical.
        int b = bid - 6144;
        int* hist = (int*)t;   // reuse smem
        for (int c = tid; c < 129; c += 256) hist[c] = 0;
        __syncthreads();
        for (int j = tid; j < Nn; j += 256) atomicAdd(&hist[g_cnt[b * Nn + j]], 1);
        __syncthreads();
        if (tid == 0) {
            int acc = 0;
            for (int c = 0; c <= 128; ++c) {
                hoff[c] = acc;
                acc += hist[c];
            }
        }
        __syncthreads();
        for (int j = tid; j < Nn; j += 256) {
            int c = g_cnt[b * Nn + j];
            int pos = atomicAdd(&hoff[c], 1);
            g_jord[b * Nn + pos] = (unsigned short)j;
        }
    }
}

// ======================= 4. prop v6b: 8-entry chunks, 16B-aligned stage =======
// CTA = (g-block 32, bp), 512 threads, occ 1.
// smem: zin [1024 i][32 g] fp32 (128 KB) + per-warp double-buffered stage
//       (2 buf x 4 j x 8 float2, 80B j-stride -> 16B-aligned cp.async dsts).
// Warp handles 4 cnt-adjacent j's (via g_jord); lane = (jj 0..3, gq 0..7).
#define PSTG_OFF (Nn * 32 * 4)         /* 131072 */
#define JSTRIDE 80                     /* bytes; 16-aligned */
#define BUFB (4 * JSTRIDE)             /* 320 B per buffer */
#define WSTG (2 * BUFB)                /* 640 B per warp */
#define PSMEM (PSTG_OFF + 16 * WSTG)   /* 141312 */

__global__ void __launch_bounds__(512, 1)
prop_kernel(int ks) {
    extern __shared__ __align__(16) char psm[];
    float* zin = (float*)psm;
    const char* stgb = psm + PSTG_OFF;
    uint32_t sb = smem_u32(psm);
    const int bp = blockIdx.y, b = bp >> 2, gb = blockIdx.x;
    const int tid = threadIdx.x, w = tid >> 5, lane = tid & 31;
    const int jj = lane >> 3, gq = lane & 7;
    const bool stager = (gq < 4);
    const size_t NN = (size_t)Nn * Nn;

    const float* src = g_zf + (size_t)bp * NN + (size_t)(ks - 1) * Gc + (size_t)gb * 32;
#pragma unroll
    for (int r = 0; r < 16; ++r) {
        int idx = r * 512 + tid;
        int row = idx >> 3, c4 = idx & 7;
        float4 v = *(const float4*)(src + (size_t)row * Nn + c4 * 4);
        *(float4*)(zin + row * 32 + c4 * 4) = v;
    }
    __syncthreads();

    const uint32_t stga = sb + PSTG_OFF + w * WSTG + jj * JSTRIDE + (gq & 3) * 16;
    const unsigned short* jordb = g_jord + b * Nn;

    for (int g0 = w * 4; g0 < Nn; g0 += 64) {
        int jl = jordb[g0 + (lane & 3)];
        int cj = g_cnt[b * Nn + jl];
        cj = max(cj, __shfl_xor_sync(0xffffffffu, cj, 1));
        cj = max(cj, __shfl_xor_sync(0xffffffffu, cj, 2));
        int jv = __shfl_sync(0xffffffffu, jl, jj);
        int nch = (cj + 7) >> 3;
        const float2* arow = g_avi + ((size_t)bp * Nn + jv) * MAXS;

        if (stager) cpa16(stga, arow + (gq & 3) * 2);
        cpa_commit();
        float4 acc0 = make_float4(0.f, 0.f, 0.f, 0.f);
        float4 acc1 = make_float4(0.f, 0.f, 0.f, 0.f);
        for (int c = 0; c < nch; ++c) {
            if (c + 1 < nch) {
                if (stager) cpa16(stga + ((c + 1) & 1) * BUFB, arow + (c + 1) * 8 + (gq & 3) * 2);
                cpa_commit();
                cpa_wait1();
            } else {
                cpa_wait0();
            }
            __syncwarp();
            const float2* bufp = (const float2*)(stgb + w * WSTG + (c & 1) * BUFB + jj * JSTRIDE);
#pragma unroll
            for (int q = 0; q < 8; ++q) {
                float2 av = bufp[q];
                int i = __float_as_int(av.y);
                float a = av.x;
                const float4 zv = *(const float4*)(zin + i * 32 + gq * 4);
                if (q & 1) {
                    acc1.x = fmaf(a, zv.x, acc1.x);
                    acc1.y = fmaf(a, zv.y, acc1.y);
                    acc1.z = fmaf(a, zv.z, acc1.z);
                    acc1.w = fmaf(a, zv.w, acc1.w);
                } else {
                    acc0.x = fmaf(a, zv.x, acc0.x);
                    acc0.y = fmaf(a, zv.y, acc0.y);
                    acc0.z = fmaf(a, zv.z, acc0.z);
                    acc0.w = fmaf(a, zv.w, acc0.w);
                }
            }
            __syncwarp();
        }
        float4 acc = make_float4(acc0.x + acc1.x, acc0.y + acc1.y,
                                 acc0.z + acc1.z, acc0.w + acc1.w);
        size_t o = ((size_t)bp * Nn + jv) * Nn + (size_t)ks * Gc + gb * 32 + gq * 4;
        *(float4*)(g_zf + o) = acc;
        __nv_bfloat16 h0, l0, h1, l1, h2, l2, h3, l3;
        split2(acc.x, h0, l0);
        split2(acc.y, h1, l1);
        split2(acc.z, h2, l2);
        split2(acc.w, h3, l3);
        __nv_bfloat162 ph01, ph23, pl01, pl23;
        ph01.x = h0; ph01.y = h1; ph23.x = h2; ph23.y = h3;
        pl01.x = l0; pl01.y = l1; pl23.x = l2; pl23.y = l3;
        *(__nv_bfloat162*)(g_zh + o) = ph01;
        *(__nv_bfloat162*)(g_zh + o + 2) = ph23;
        *(__nv_bfloat162*)(g_zl + o) = pl01;
        *(__nv_bfloat162*)(g_zl + o + 2) = pl23;
    }
}

// ======================= 5. HMMA filter GEMM ===================================
#define TBK 32
#define NCH (Nn / TBK)
#define ASTG 16384
#define BSTG 16384
#define STG (ASTG + BSTG)
#define NSTAGE 3
#define SMEM_GEMM (NSTAGE * STG)

__global__ void __launch_bounds__(256, 2)
mma_gemm(const float* __restrict__ bias, float* __restrict__ out) {
    extern __shared__ __align__(1024) char smem[];
    uint32_t sb = smem_u32(smem);
    const int bp = blockIdx.z, p = bp & 3;
    const int m0 = blockIdx.y * 128, n0 = blockIdx.x * 128;
    const int tid = threadIdx.x, wid = tid >> 5, lane = tid & 31;
    const int warp_m = wid >> 2, warp_n = wid & 3;
    const size_t NN = (size_t)Nn * Nn;

    const __nv_bfloat16* Ah = g_fwh + (size_t)p * Fc * Nn;
    const __nv_bfloat16* Al = g_fwl + (size_t)p * Fc * Nn;
    const __nv_bfloat16* Bh = g_zh + (size_t)bp * NN;
    const __nv_bfloat16* Bl = g_zl + (size_t)bp * NN;

    float acc[4][4][4];
#pragma unroll
    for (int i = 0; i < 4; ++i)
#pragma unroll
        for (int j = 0; j < 4; ++j)
#pragma unroll
            for (int q = 0; q < 4; ++q) acc[i][j][q] = 0.f;

    auto load_stage = [&](int c, int s) {
        uint32_t base = sb + s * STG;
        int k0 = c * TBK;
#pragma unroll
        for (int i = 0; i < 4; ++i) {
            int idx = i * 256 + tid;
            int r = idx >> 3, ch = idx & 7;
            const __nv_bfloat16* srcp = ((ch < 4) ? Ah : Al) + (size_t)(m0 + r) * Nn + k0 + (ch & 3) * 8;
            cpa16(base + SWZ(r * 128 + ch * 16), srcp);
        }
#pragma unroll
        for (int i = 0; i < 4; ++i) {
            int idx = i * 256 + tid;
            int r = idx >> 3, ch = idx & 7;
            const __nv_bfloat16* srcp = ((ch < 4) ? Bh : Bl) + (size_t)(n0 + r) * Nn + k0 + (ch & 3) * 8;
            cpa16(base + ASTG + SWZ(r * 128 + ch * 16), srcp);
        }
        cpa_commit();
    };

    const int a_row = (lane & 7) + ((lane >> 3) & 1) * 8;
    const int a_k16 = lane >> 4;
    const int b_row = (lane & 7);
    const int b_par = (lane >> 3) & 1;

    load_stage(0, 0);
    load_stage(1, 1);
    for (int c = 0; c < NCH; ++c) {
        if (c + 2 < NCH) {
            load_stage(c + 2, (c + 2) % NSTAGE);
            cpa_wait2();
        } else if (c + 1 < NCH) {
            cpa_wait1();
        } else {
            cpa_wait0();
        }
        __syncthreads();
        uint32_t Abase = sb + (c % NSTAGE) * STG;
        uint32_t Bbase = Abase + ASTG;
#pragma unroll
        for (int s = 0; s < 2; ++s) {
            uint32_t bh2[4][2], bl2[4][2];
#pragma unroll
            for (int o = 0; o < 4; ++o) {
                int row = warp_n * 32 + o * 8 + b_row;
                int chk = s * 2 + b_par;
                ldm_x2(bh2[o][0], bh2[o][1], Bbase + SWZ(row * 128 + chk * 16));
                ldm_x2(bl2[o][0], bl2[o][1], Bbase + SWZ(row * 128 + 64 + chk * 16));
            }
            uint32_t ah[4][4], al[4][4];
#pragma unroll
            for (int mt = 0; mt < 4; ++mt) {
                int row = warp_m * 64 + mt * 16 + a_row;
                int chh = s * 2 + a_k16;
                ldm_x4(ah[mt][0], ah[mt][1], ah[mt][2], ah[mt][3],
                       Abase + SWZ(row * 128 + chh * 16));
                ldm_x4(al[mt][0], al[mt][1], al[mt][2], al[mt][3],
                       Abase + SWZ(row * 128 + 64 + chh * 16));
            }
#pragma unroll
            for (int mt = 0; mt < 4; ++mt)
#pragma unroll
                for (int o = 0; o < 4; ++o) mma16816(acc[mt][o], ah[mt], bh2[o]);
#pragma unroll
            for (int mt = 0; mt < 4; ++mt)
#pragma unroll
                for (int o = 0; o < 4; ++o) mma16816(acc[mt][o], ah[mt], bl2[o]);
#pragma unroll
            for (int mt = 0; mt < 4; ++mt)
#pragma unroll
                for (int o = 0; o < 4; ++o) mma16816(acc[mt][o], al[mt], bh2[o]);
        }
        __syncthreads();
    }

    float* C = out + (size_t)bp * Fc * Nn;
    const int r_base = m0 + warp_m * 64 + (lane >> 2);
    const int c_base = n0 + warp_n * 32 + (lane & 3) * 2;
#pragma unroll
    for (int mt = 0; mt < 4; ++mt)
#pragma unroll
        for (int o = 0; o < 4; ++o) {
#pragma unroll
            for (int h = 0; h < 2; ++h) {
                int r = r_base + mt * 16 + h * 8;
                int cc = c_base + o * 8;
                float bv = bias[r];
                float t0 = acc[mt][o][2 * h] + bv;
                float t1 = acc[mt][o][2 * h + 1] + bv;
                t0 = t0 > 0.f ? t0 : 0.01f * t0;
                t1 = t1 > 0.f ? t1 : 0.01f * t1;
                *(float2*)(C + (size_t)r * Nn + cc) = make_float2(t0, t1);
            }
        }
}

// ======================= launch ================================================
extern "C" void kernel_launch(void* const* d_in, const int* in_sizes, int n_in,
                              void* d_out, int out_size) {
    const float* x      = (const float*)d_in[0];
    const float* mixer  = (const float*)d_in[1];
    const float* weight = (const float*)d_in[2];
    const float* wb     = (const float*)d_in[3];
    const float* fw     = (const float*)d_in[4];
    const float* bias   = (const float*)d_in[5];
    const float* S      = (const float*)d_in[6];
    float* out = (float*)d_out;

    cudaFuncSetAttribute(mma_gemm, cudaFuncAttributeMaxDynamicSharedMemorySize, SMEM_GEMM);
    cudaFuncSetAttribute(prop_kernel, cudaFuncAttributeMaxDynamicSharedMemorySize, PSMEM);

    peidx_kernel<<<384, 256>>>(x, mixer, weight, wb, S);       // 1
    ms_kernel<<<dim3(Nn, Bc), 256>>>(S);                       // 2
    fillsplit_kernel<<<6152, 256>>>(x, fw);                    // 3 (+ cnt-sort)
    for (int k = 1; k < Kc; ++k)                               // 4 (profiled), 5, 6
        prop_kernel<<<dim3(8, NBP), 512, PSMEM>>>(k);
    mma_gemm<<<dim3(Nn / 128, Fc / 128, NBP), 256, SMEM_GEMM>>>(bias, out);  // 7
}

// round 16
// speedup vs baseline: 1.0574x; 1.0238x over previous
#include <cuda_runtime.h>
#include <cuda_bf16.h>
#include <cstdint>

#define Bc 8
#define Gc 256
#define Nn 1024
#define Pc 4
#define Fc 256
#define Kc 4
#define NBP 32
#define MAXS 128

// ======================= device scratch ======================================
__device__ float g_e1[NBP * Nn];
__device__ float g_e2[NBP * Nn];
__device__ float g_m[NBP * Nn];
__device__ float g_s[NBP * Nn];
__device__ int g_cnt[Bc * Nn];
__device__ unsigned short g_idx[(size_t)Bc * Nn * MAXS];    // 2 MB
__device__ unsigned short g_jord[Bc * Nn];                  // cnt-sorted column order
__device__ float2 g_avi[(size_t)NBP * Nn * MAXS];           // 32 MB (value, i-bits)
__device__ float g_zf[(size_t)NBP * Nn * Nn];               // zT fp32 [bp][n][kG] (slices 1-3)
__device__ __nv_bfloat16 g_zh[(size_t)NBP * Nn * Nn];       // zT hi (slices 1-3)
__device__ __nv_bfloat16 g_zl[(size_t)NBP * Nn * Nn];       // zT lo (slices 1-3)
__device__ float g_xT[(size_t)Bc * Nn * Gc];                // 8 MB x^T per b [n][g]
__device__ __nv_bfloat16 g_xTh[(size_t)Bc * Nn * Gc];       // 4 MB
__device__ __nv_bfloat16 g_xTl[(size_t)Bc * Nn * Gc];       // 4 MB
__device__ __nv_bfloat16 g_fwh[(size_t)Pc * Fc * Kc * Gc];
__device__ __nv_bfloat16 g_fwl[(size_t)Pc * Fc * Kc * Gc];

__device__ __forceinline__ void split2(float v, __nv_bfloat16& h, __nv_bfloat16& l) {
    h = __float2bfloat16(v);
    l = __float2bfloat16(v - __bfloat162float(h));
}

// ======================= helpers =============================================
__device__ __forceinline__ uint32_t smem_u32(const void* p) {
    uint32_t a;
    asm("{ .reg .u64 t; cvta.to.shared.u64 t, %1; cvt.u32.u64 %0, t; }" : "=r"(a) : "l"(p));
    return a;
}
__device__ __forceinline__ void cpa16(uint32_t dst, const void* src) {
    asm volatile("cp.async.cg.shared.global [%0], [%1], 16;" :: "r"(dst), "l"(src));
}
__device__ __forceinline__ void cpa_commit() { asm volatile("cp.async.commit_group;" ::: "memory"); }
__device__ __forceinline__ void cpa_wait2() { asm volatile("cp.async.wait_group 2;" ::: "memory"); }
__device__ __forceinline__ void cpa_wait1() { asm volatile("cp.async.wait_group 1;" ::: "memory"); }
__device__ __forceinline__ void cpa_wait0() { asm volatile("cp.async.wait_group 0;" ::: "memory"); }

#define SWZ(off) ((off) ^ (((off) >> 3) & 0x70))

__device__ __forceinline__ void ldm_x4(uint32_t& r0, uint32_t& r1, uint32_t& r2, uint32_t& r3,
                                       uint32_t addr) {
    asm volatile("ldmatrix.sync.aligned.m8n8.x4.shared.b16 {%0,%1,%2,%3}, [%4];"
                 : "=r"(r0), "=r"(r1), "=r"(r2), "=r"(r3) : "r"(addr));
}
__device__ __forceinline__ void ldm_x2(uint32_t& r0, uint32_t& r1, uint32_t addr) {
    asm volatile("ldmatrix.sync.aligned.m8n8.x2.shared.b16 {%0,%1}, [%2];"
                 : "=r"(r0), "=r"(r1) : "r"(addr));
}
__device__ __forceinline__ void mma16816(float* c, const uint32_t* a, const uint32_t* b) {
    asm volatile(
        "mma.sync.aligned.m16n8k16.row.col.f32.bf16.bf16.f32 "
        "{%0,%1,%2,%3}, {%4,%5,%6,%7}, {%8,%9}, {%0,%1,%2,%3};"
        : "+f"(c[0]), "+f"(c[1]), "+f"(c[2]), "+f"(c[3])
        : "r"(a[0]), "r"(a[1]), "r"(a[2]), "r"(a[3]), "r"(b[0]), "r"(b[1]));
}

// ======================= reductions ==========================================
__device__ __forceinline__ float blockReduceMax(float v, float* sm) {
#pragma unroll
    for (int o = 16; o; o >>= 1) v = fmaxf(v, __shfl_xor_sync(0xffffffffu, v, o));
    if ((threadIdx.x & 31) == 0) sm[threadIdx.x >> 5] = v;
    __syncthreads();
    if (threadIdx.x < 32) {
        float t = (threadIdx.x < 8) ? sm[threadIdx.x] : -3.0e38f;
#pragma unroll
        for (int o = 4; o; o >>= 1) t = fmaxf(t, __shfl_xor_sync(0xffffffffu, t, o));
        if (threadIdx.x == 0) sm[0] = t;
    }
    __syncthreads();
    float r = sm[0];
    __syncthreads();
    return r;
}
__device__ __forceinline__ float blockReduceSum(float v, float* sm) {
#pragma unroll
    for (int o = 16; o; o >>= 1) v += __shfl_xor_sync(0xffffffffu, v, o);
    if ((threadIdx.x & 31) == 0) sm[threadIdx.x >> 5] = v;
    __syncthreads();
    if (threadIdx.x < 32) {
        float t = (threadIdx.x < 8) ? sm[threadIdx.x] : 0.f;
#pragma unroll
        for (int o = 4; o; o >>= 1) t += __shfl_xor_sync(0xffffffffu, t, o);
        if (threadIdx.x == 0) sm[0] = t;
    }
    __syncthreads();
    float r = sm[0];
    __syncthreads();
    return r;
}

// ======================= 1. fused pe + idxT ====================================
__global__ void peidx_kernel(const float* __restrict__ x,
                             const float* __restrict__ mixer,
                             const float* __restrict__ weight,
                             const float* __restrict__ wb,
                             const float* __restrict__ S) {
    __shared__ __align__(16) char sbuf[4352];
    __shared__ int ccnt[32];
    int bid = blockIdx.x, tid = threadIdx.x;
    if (bid < 128) {
        int bp = bid >> 2;
        int b = bp >> 2, p = bp & 3;
        float* s1 = (float*)sbuf;
        float* s2 = s1 + Gc;
        float* sc = (float*)ccnt;
        {
            int g = tid;
            float v1 = 0.f, v2 = 0.f;
            const float* mw1 = mixer + p * 2 * Fc;
            const float* mw2 = mw1 + Fc;
#pragma unroll 8
            for (int f = 0; f < Fc; ++f) {
                float w = weight[((size_t)(p * Fc + f)) * Gc + g];
                v1 = fmaf(mw1[f], w, v1);
                v2 = fmaf(mw2[f], w, v2);
            }
            s1[g] = v1;
            s2[g] = v2;
            if (g == 0) {
                float c1 = 0.f, c2 = 0.f;
                for (int f = 0; f < Fc; ++f) {
                    c1 = fmaf(mw1[f], wb[p * Fc + f], c1);
                    c2 = fmaf(mw2[f], wb[p * Fc + f], c2);
                }
                sc[0] = c1;
                sc[1] = c2;
            }
        }
        __syncthreads();
        int n = (bid & 3) * 256 + tid;
        const float* xb = x + (size_t)b * Gc * Nn + n;
        float a1 = 0.f, a2 = 0.f;
#pragma unroll 8
        for (int g = 0; g < Gc; ++g) {
            float xv = xb[(size_t)g * Nn];
            a1 = fmaf(s1[g], xv, a1);
            a2 = fmaf(s2[g], xv, a2);
        }
        g_e1[bp * Nn + n] = a1 + sc[0];
        g_e2[bp * Nn + n] = a2 + sc[1];
    } else {
        int fb = bid - 128;
        int b = fb >> 5;
        int j0 = (fb & 31) * 32;
        float(*tile)[33] = (float(*)[33])sbuf;
        int tx = tid & 31, ty = tid >> 5;
        if (tid < 32) ccnt[tid] = 0;
        __syncthreads();
        const float* Sb = S + (size_t)b * Nn * Nn;
        for (int it = 0; it < 32; ++it) {
            int i0 = it * 32;
#pragma unroll
            for (int q = 0; q < 4; ++q) {
                int r = ty + q * 8;
                tile[r][tx] = Sb[(size_t)(i0 + r) * Nn + j0 + tx];
            }
            __syncthreads();
            if (tid < 32) {
                int j = j0 + tid;
                int c = ccnt[tid];
                unsigned short* ip = g_idx + ((size_t)b * Nn + j) * MAXS;
#pragma unroll 8
                for (int r = 0; r < 32; ++r) {
                    if (fabsf(tile[r][tid]) > 1e-9f) {
                        if (c < MAXS) ip[c] = (unsigned short)(i0 + r);
                        ++c;
                    }
                }
                ccnt[tid] = c;
            }
            __syncthreads();
        }
        if (tid < 32) g_cnt[b * Nn + j0 + tid] = ccnt[tid] < MAXS ? ccnt[tid] : MAXS;
    }
}

// ======================= 2. ms + cnt-sort =====================================
// blockIdx.x < Nn: per-row softmax stats (4 p per block).
// blockIdx.x == Nn: counting sort of columns by cnt for b = blockIdx.y.
__global__ void ms_kernel(const float* __restrict__ S) {
    __shared__ float sm[8];
    __shared__ int hist[129];
    __shared__ int hoff[129];
    int i = blockIdx.x, b = blockIdx.y, tid = threadIdx.x;
    if (i == Nn) {
        for (int c = tid; c < 129; c += 256) hist[c] = 0;
        __syncthreads();
        for (int j = tid; j < Nn; j += 256) atomicAdd(&hist[g_cnt[b * Nn + j]], 1);
        __syncthreads();
        if (tid == 0) {
            int acc = 0;
            for (int c = 0; c <= 128; ++c) {
                hoff[c] = acc;
                acc += hist[c];
            }
        }
        __syncthreads();
        for (int j = tid; j < Nn; j += 256) {
            int c = g_cnt[b * Nn + j];
            int pos = atomicAdd(&hoff[c], 1);
            g_jord[b * Nn + pos] = (unsigned short)j;
        }
        return;
    }
    const float* Sr = S + ((size_t)b * Nn + i) * Nn;
    int mk[4];
    float lv[4][4];
    float e2i[4];
#pragma unroll
    for (int p = 0; p < 4; ++p) e2i[p] = g_e2[(b * 4 + p) * Nn + i];
#pragma unroll
    for (int q = 0; q < 4; ++q) {
        int j = tid + q * 256;
        mk[q] = (fabsf(Sr[j]) > 1e-9f);
#pragma unroll
        for (int p = 0; p < 4; ++p) {
            float e = g_e1[(b * 4 + p) * Nn + j] + e2i[p];
            lv[p][q] = e > 0.f ? e : 0.2f * e;
        }
    }
#pragma unroll
    for (int p = 0; p < 4; ++p) {
        float vmax = -3.0e38f;
#pragma unroll
        for (int q = 0; q < 4; ++q)
            if (mk[q]) vmax = fmaxf(vmax, lv[p][q]);
        vmax = blockReduceMax(vmax, sm);
        float sum = 0.f;
#pragma unroll
        for (int q = 0; q < 4; ++q)
            sum += mk[q] ? __expf(lv[p][q] - vmax) : 0.f;
        sum = blockReduceSum(sum, sm);
        if (tid == 0) {
            g_m[(b * 4 + p) * Nn + i] = vmax;
            g_s[(b * 4 + p) * Nn + i] = sum;
        }
    }
}

// ======================= 3. fused fill + split =================================
// bid < 4096: fill by sorted position (writes only up to group-padded limit)
// bid >= 4096: x -> xT fp32/hi/lo per b (no per-p replication), + fw split
__global__ void fillsplit_kernel(const float* __restrict__ x, const float* __restrict__ fw) {
    __shared__ float t[32][33];
    int bid = blockIdx.x, tid = threadIdx.x;
    if (bid < 4096) {
        int bp = bid >> 7, b = bp >> 2;
        int w = tid >> 5, lane = tid & 31;
        int pos = (bid & 127) * 8 + w;
        int grp = pos & ~3;
        const unsigned short* jordb = g_jord + b * Nn;
        int j = jordb[pos];
        int gmax = 0;
#pragma unroll
        for (int q = 0; q < 4; ++q) {
            int cq = g_cnt[b * Nn + jordb[grp + q]];
            gmax = max(gmax, cq);
        }
        int wlim = (gmax + 7) & ~7;
        int cnt = g_cnt[b * Nn + j];
        float e1j = g_e1[bp * Nn + j];
        const unsigned short* ip = g_idx + ((size_t)b * Nn + j) * MAXS;
        float2* ap = g_avi + ((size_t)bp * Nn + j) * MAXS;
        for (int s = lane; s < wlim; s += 32) {
            float2 o = make_float2(0.f, __int_as_float(0));
            if (s < cnt) {
                int i = ip[s];
                float e = e1j + g_e2[bp * Nn + i];
                float l = e > 0.f ? e : 0.2f * e;
                o = make_float2(__expf(l - g_m[bp * Nn + i]) / g_s[bp * Nn + i], __int_as_float(i));
            }
            ap[s] = o;
        }
    } else {
        int sbid = bid - 4096;
        int b = sbid >> 8;
        int g0 = ((sbid >> 5) & 7) * 32, n0 = (sbid & 31) * 32;
        int tx = tid & 31, ty = tid >> 5;
        const float* xp = x + ((size_t)b * Gc + g0) * Nn + n0;
#pragma unroll
        for (int q = 0; q < 4; ++q) {
            int g = ty + q * 8;
            t[g][tx] = xp[(size_t)g * Nn + tx];
        }
        __syncthreads();
#pragma unroll
        for (int q = 0; q < 4; ++q) {
            int nn = ty + q * 8;
            float v = t[tx][nn];
            __nv_bfloat16 h, l;
            split2(v, h, l);
            size_t o = ((size_t)b * Nn + n0 + nn) * Gc + g0 + tx;
            g_xT[o] = v;
            g_xTh[o] = h;
            g_xTl[o] = l;
        }
        const int FT = Pc * Fc * Kc * Gc;
        int tot = 2048 * 256;
        int gid = sbid * 256 + tid;
        for (int i = gid; i < FT; i += tot) {
            __nv_bfloat16 h, l;
            split2(fw[i], h, l);
            g_fwh[i] = h;
            g_fwl[i] = l;
        }
    }
}

// ======================= 4. prop: 8-entry chunks, sorted j grouping ===========
#define PSTG_OFF (Nn * 32 * 4)         /* 131072 */
#define JSTRIDE 80
#define BUFB (4 * JSTRIDE)
#define WSTG (2 * BUFB)
#define PSMEM (PSTG_OFF + 16 * WSTG)

__global__ void __launch_bounds__(512, 1)
prop_kernel(int ks) {
    extern __shared__ __align__(16) char psm[];
    float* zin = (float*)psm;
    const char* stgb = psm + PSTG_OFF;
    uint32_t sb = smem_u32(psm);
    const int bp = blockIdx.y, b = bp >> 2, gb = blockIdx.x;
    const int tid = threadIdx.x, w = tid >> 5, lane = tid & 31;
    const int jj = lane >> 3, gq = lane & 7;
    const bool stager = (gq < 4);
    const size_t NN = (size_t)Nn * Nn;

    const float* src;
    int sstride;
    if (ks == 1) {
        src = g_xT + (size_t)b * Nn * Gc + gb * 32;
        sstride = Gc;
    } else {
        src = g_zf + (size_t)bp * NN + (size_t)(ks - 1) * Gc + (size_t)gb * 32;
        sstride = Nn;
    }
#pragma unroll
    for (int r = 0; r < 16; ++r) {
        int idx = r * 512 + tid;
        int row = idx >> 3, c4 = idx & 7;
        float4 v = *(const float4*)(src + (size_t)row * sstride + c4 * 4);
        *(float4*)(zin + row * 32 + c4 * 4) = v;
    }
    __syncthreads();

    const uint32_t stga = sb + PSTG_OFF + w * WSTG + jj * JSTRIDE + (gq & 3) * 16;
    const unsigned short* jordb = g_jord + b * Nn;

    for (int g0 = w * 4; g0 < Nn; g0 += 64) {
        int jl = jordb[g0 + (lane & 3)];
        int cj = g_cnt[b * Nn + jl];
        cj = max(cj, __shfl_xor_sync(0xffffffffu, cj, 1));
        cj = max(cj, __shfl_xor_sync(0xffffffffu, cj, 2));
        int jv = __shfl_sync(0xffffffffu, jl, jj);
        int nch = (cj + 7) >> 3;
        const float2* arow = g_avi + ((size_t)bp * Nn + jv) * MAXS;

        if (stager) cpa16(stga, arow + (gq & 3) * 2);
        cpa_commit();
        float4 acc0 = make_float4(0.f, 0.f, 0.f, 0.f);
        float4 acc1 = make_float4(0.f, 0.f, 0.f, 0.f);
        for (int c = 0; c < nch; ++c) {
            if (c + 1 < nch) {
                if (stager) cpa16(stga + ((c + 1) & 1) * BUFB, arow + (c + 1) * 8 + (gq & 3) * 2);
                cpa_commit();
                cpa_wait1();
            } else {
                cpa_wait0();
            }
            __syncwarp();
            const float2* bufp = (const float2*)(stgb + w * WSTG + (c & 1) * BUFB + jj * JSTRIDE);
#pragma unroll
            for (int q = 0; q < 8; ++q) {
                float2 av = bufp[q];
                int i = __float_as_int(av.y);
                float a = av.x;
                const float4 zv = *(const float4*)(zin + i * 32 + gq * 4);
                if (q & 1) {
                    acc1.x = fmaf(a, zv.x, acc1.x);
                    acc1.y = fmaf(a, zv.y, acc1.y);
                    acc1.z = fmaf(a, zv.z, acc1.z);
                    acc1.w = fmaf(a, zv.w, acc1.w);
                } else {
                    acc0.x = fmaf(a, zv.x, acc0.x);
                    acc0.y = fmaf(a, zv.y, acc0.y);
                    acc0.z = fmaf(a, zv.z, acc0.z);
                    acc0.w = fmaf(a, zv.w, acc0.w);
                }
            }
            __syncwarp();
        }
        float4 acc = make_float4(acc0.x + acc1.x, acc0.y + acc1.y,
                                 acc0.z + acc1.z, acc0.w + acc1.w);
        size_t o = ((size_t)bp * Nn + jv) * Nn + (size_t)ks * Gc + gb * 32 + gq * 4;
        *(float4*)(g_zf + o) = acc;
        __nv_bfloat16 h0, l0, h1, l1, h2, l2, h3, l3;
        split2(acc.x, h0, l0);
        split2(acc.y, h1, l1);
        split2(acc.z, h2, l2);
        split2(acc.w, h3, l3);
        __nv_bfloat162 ph01, ph23, pl01, pl23;
        ph01.x = h0; ph01.y = h1; ph23.x = h2; ph23.y = h3;
        pl01.x = l0; pl01.y = l1; pl23.x = l2; pl23.y = l3;
        *(__nv_bfloat162*)(g_zh + o) = ph01;
        *(__nv_bfloat162*)(g_zh + o + 2) = ph23;
        *(__nv_bfloat162*)(g_zl + o) = pl01;
        *(__nv_bfloat162*)(g_zl + o + 2) = pl23;
    }
}

// ======================= 5. HMMA filter GEMM ===================================
// B slice 0 (k<256) comes from shared per-b xTh/xTl (stride Gc); slices 1-3
// from per-bp zh/zl (stride Nn). Each BK=32 stage lies in exactly one slice.
#define TBK 32
#define NCH (Nn / TBK)
#define ASTG 16384
#define BSTG 16384
#define STG (ASTG + BSTG)
#define NSTAGE 3
#define SMEM_GEMM (NSTAGE * STG)

__global__ void __launch_bounds__(256, 2)
mma_gemm(const float* __restrict__ bias, float* __restrict__ out) {
    extern __shared__ __align__(1024) char smem[];
    uint32_t sb = smem_u32(smem);
    const int bp = blockIdx.z, p = bp & 3, b = bp >> 2;
    const int m0 = blockIdx.y * 128, n0 = blockIdx.x * 128;
    const int tid = threadIdx.x, wid = tid >> 5, lane = tid & 31;
    const int warp_m = wid >> 2, warp_n = wid & 3;
    const size_t NN = (size_t)Nn * Nn;

    const __nv_bfloat16* Ah = g_fwh + (size_t)p * Fc * Nn;
    const __nv_bfloat16* Al = g_fwl + (size_t)p * Fc * Nn;
    const __nv_bfloat16* Bh1 = g_zh + (size_t)bp * NN;
    const __nv_bfloat16* Bl1 = g_zl + (size_t)bp * NN;
    const __nv_bfloat16* Bh0 = g_xTh + (size_t)b * Nn * Gc;
    const __nv_bfloat16* Bl0 = g_xTl + (size_t)b * Nn * Gc;

    float acc[4][4][4];
#pragma unroll
    for (int i = 0; i < 4; ++i)
#pragma unroll
        for (int j = 0; j < 4; ++j)
#pragma unroll
            for (int q = 0; q < 4; ++q) acc[i][j][q] = 0.f;

    auto load_stage = [&](int c, int s) {
        uint32_t base = sb + s * STG;
        int k0 = c * TBK;
        bool sl0 = (c < 8);
        const __nv_bfloat16* bh = sl0 ? Bh0 : Bh1;
        const __nv_bfloat16* bl = sl0 ? Bl0 : Bl1;
        int bstride = sl0 ? Gc : Nn;
#pragma unroll
        for (int i = 0; i < 4; ++i) {
            int idx = i * 256 + tid;
            int r = idx >> 3, ch = idx & 7;
            const __nv_bfloat16* srcp = ((ch < 4) ? Ah : Al) + (size_t)(m0 + r) * Nn + k0 + (ch & 3) * 8;
            cpa16(base + SWZ(r * 128 + ch * 16), srcp);
        }
#pragma unroll
        for (int i = 0; i < 4; ++i) {
            int idx = i * 256 + tid;
            int r = idx >> 3, ch = idx & 7;
            const __nv_bfloat16* srcp = ((ch < 4) ? bh : bl) + (size_t)(n0 + r) * bstride + k0 + (ch & 3) * 8;
            cpa16(base + ASTG + SWZ(r * 128 + ch * 16), srcp);
        }
        cpa_commit();
    };

    const int a_row = (lane & 7) + ((lane >> 3) & 1) * 8;
    const int a_k16 = lane >> 4;
    const int b_row = (lane & 7);
    const int b_par = (lane >> 3) & 1;

    load_stage(0, 0);
    load_stage(1, 1);
    for (int c = 0; c < NCH; ++c) {
        if (c + 2 < NCH) {
            load_stage(c + 2, (c + 2) % NSTAGE);
            cpa_wait2();
        } else if (c + 1 < NCH) {
            cpa_wait1();
        } else {
            cpa_wait0();
        }
        __syncthreads();
        uint32_t Abase = sb + (c % NSTAGE) * STG;
        uint32_t Bbase = Abase + ASTG;
#pragma unroll
        for (int s = 0; s < 2; ++s) {
            uint32_t bh2[4][2], bl2[4][2];
#pragma unroll
            for (int o = 0; o < 4; ++o) {
                int row = warp_n * 32 + o * 8 + b_row;
                int chk = s * 2 + b_par;
                ldm_x2(bh2[o][0], bh2[o][1], Bbase + SWZ(row * 128 + chk * 16));
                ldm_x2(bl2[o][0], bl2[o][1], Bbase + SWZ(row * 128 + 64 + chk * 16));
            }
            uint32_t ah[4][4], al[4][4];
#pragma unroll
            for (int mt = 0; mt < 4; ++mt) {
                int row = warp_m * 64 + mt * 16 + a_row;
                int chh = s * 2 + a_k16;
                ldm_x4(ah[mt][0], ah[mt][1], ah[mt][2], ah[mt][3],
                       Abase + SWZ(row * 128 + chh * 16));
                ldm_x4(al[mt][0], al[mt][1], al[mt][2], al[mt][3],
                       Abase + SWZ(row * 128 + 64 + chh * 16));
            }
#pragma unroll
            for (int mt = 0; mt < 4; ++mt)
#pragma unroll
                for (int o = 0; o < 4; ++o) mma16816(acc[mt][o], ah[mt], bh2[o]);
#pragma unroll
            for (int mt = 0; mt < 4; ++mt)
#pragma unroll
                for (int o = 0; o < 4; ++o) mma16816(acc[mt][o], ah[mt], bl2[o]);
#pragma unroll
            for (int mt = 0; mt < 4; ++mt)
#pragma unroll
                for (int o = 0; o < 4; ++o) mma16816(acc[mt][o], al[mt], bh2[o]);
        }
        __syncthreads();
    }

    float* C = out + (size_t)bp * Fc * Nn;
    const int r_base = m0 + warp_m * 64 + (lane >> 2);
    const int c_base = n0 + warp_n * 32 + (lane & 3) * 2;
#pragma unroll
    for (int mt = 0; mt < 4; ++mt)
#pragma unroll
        for (int o = 0; o < 4; ++o) {
#pragma unroll
            for (int h = 0; h < 2; ++h) {
                int r = r_base + mt * 16 + h * 8;
                int cc = c_base + o * 8;
                float bv = bias[r];
                float t0 = acc[mt][o][2 * h] + bv;
                float t1 = acc[mt][o][2 * h + 1] + bv;
                t0 = t0 > 0.f ? t0 : 0.01f * t0;
                t1 = t1 > 0.f ? t1 : 0.01f * t1;
                *(float2*)(C + (size_t)r * Nn + cc) = make_float2(t0, t1);
            }
        }
}

// ======================= launch ================================================
extern "C" void kernel_launch(void* const* d_in, const int* in_sizes, int n_in,
                              void* d_out, int out_size) {
    const float* x      = (const float*)d_in[0];
    const float* mixer  = (const float*)d_in[1];
    const float* weight = (const float*)d_in[2];
    const float* wb     = (const float*)d_in[3];
    const float* fw     = (const float*)d_in[4];
    const float* bias   = (const float*)d_in[5];
    const float* S      = (const float*)d_in[6];
    float* out = (float*)d_out;

    cudaFuncSetAttribute(mma_gemm, cudaFuncAttributeMaxDynamicSharedMemorySize, SMEM_GEMM);
    cudaFuncSetAttribute(prop_kernel, cudaFuncAttributeMaxDynamicSharedMemorySize, PSMEM);

    peidx_kernel<<<384, 256>>>(x, mixer, weight, wb, S);       // 1
    ms_kernel<<<dim3(Nn + 1, Bc), 256>>>(S);                   // 2 (stats + cnt-sort)
    fillsplit_kernel<<<6144, 256>>>(x, fw);                    // 3
    for (int k = 1; k < Kc; ++k)                               // 4 (profiled), 5, 6
        prop_kernel<<<dim3(8, NBP), 512, PSMEM>>>(k);
    mma_gemm<<<dim3(Nn / 128, Fc / 128, NBP), 256, SMEM_GEMM>>>(bias, out);  // 7
}

// round 17
// speedup vs baseline: 1.1748x; 1.1110x over previous
#include <cuda_runtime.h>
#include <cuda_bf16.h>
#include <cstdint>

#define Bc 8
#define Gc 256
#define Nn 1024
#define Pc 4
#define Fc 256
#define Kc 4
#define NBP 32
#define MAXS 128

// ======================= device scratch ======================================
__device__ float g_e1[NBP * Nn];
__device__ float g_e2[NBP * Nn];
__device__ float g_m[NBP * Nn];
__device__ float g_s[NBP * Nn];
__device__ int g_cnt[Bc * Nn];
__device__ unsigned short g_idx[(size_t)Bc * Nn * MAXS];    // 2 MB
__device__ unsigned short g_jord[Bc * Nn];                  // cnt-sorted column order
__device__ float2 g_avi[(size_t)NBP * Nn * MAXS];           // 32 MB (value, i-bits) per bp
__device__ float4 g_av4[(size_t)Bc * Nn * MAXS];            // 16 MB packed a for 4 p
__device__ int g_ii[(size_t)Bc * Nn * MAXS];                // 4 MB packed i-stream
__device__ float g_zf[(size_t)NBP * Nn * Nn];               // zT fp32 [bp][n][kG] (slices 1-3)
__device__ __nv_bfloat16 g_zh[(size_t)NBP * Nn * Nn];       // zT hi
__device__ __nv_bfloat16 g_zl[(size_t)NBP * Nn * Nn];       // zT lo
__device__ float g_xT[(size_t)Bc * Nn * Gc];                // 8 MB x^T per b [n][g]
__device__ __nv_bfloat16 g_xTh[(size_t)Bc * Nn * Gc];
__device__ __nv_bfloat16 g_xTl[(size_t)Bc * Nn * Gc];
__device__ __nv_bfloat16 g_fwh[(size_t)Pc * Fc * Kc * Gc];
__device__ __nv_bfloat16 g_fwl[(size_t)Pc * Fc * Kc * Gc];

__device__ __forceinline__ void split2(float v, __nv_bfloat16& h, __nv_bfloat16& l) {
    h = __float2bfloat16(v);
    l = __float2bfloat16(v - __bfloat162float(h));
}

// ======================= helpers =============================================
__device__ __forceinline__ uint32_t smem_u32(const void* p) {
    uint32_t a;
    asm("{ .reg .u64 t; cvta.to.shared.u64 t, %1; cvt.u32.u64 %0, t; }" : "=r"(a) : "l"(p));
    return a;
}
__device__ __forceinline__ void cpa16(uint32_t dst, const void* src) {
    asm volatile("cp.async.cg.shared.global [%0], [%1], 16;" :: "r"(dst), "l"(src));
}
__device__ __forceinline__ void cpa_commit() { asm volatile("cp.async.commit_group;" ::: "memory"); }
__device__ __forceinline__ void cpa_wait2() { asm volatile("cp.async.wait_group 2;" ::: "memory"); }
__device__ __forceinline__ void cpa_wait1() { asm volatile("cp.async.wait_group 1;" ::: "memory"); }
__device__ __forceinline__ void cpa_wait0() { asm volatile("cp.async.wait_group 0;" ::: "memory"); }

#define SWZ(off) ((off) ^ (((off) >> 3) & 0x70))

__device__ __forceinline__ void ldm_x4(uint32_t& r0, uint32_t& r1, uint32_t& r2, uint32_t& r3,
                                       uint32_t addr) {
    asm volatile("ldmatrix.sync.aligned.m8n8.x4.shared.b16 {%0,%1,%2,%3}, [%4];"
                 : "=r"(r0), "=r"(r1), "=r"(r2), "=r"(r3) : "r"(addr));
}
__device__ __forceinline__ void ldm_x2(uint32_t& r0, uint32_t& r1, uint32_t addr) {
    asm volatile("ldmatrix.sync.aligned.m8n8.x2.shared.b16 {%0,%1}, [%2];"
                 : "=r"(r0), "=r"(r1) : "r"(addr));
}
__device__ __forceinline__ void mma16816(float* c, const uint32_t* a, const uint32_t* b) {
    asm volatile(
        "mma.sync.aligned.m16n8k16.row.col.f32.bf16.bf16.f32 "
        "{%0,%1,%2,%3}, {%4,%5,%6,%7}, {%8,%9}, {%0,%1,%2,%3};"
        : "+f"(c[0]), "+f"(c[1]), "+f"(c[2]), "+f"(c[3])
        : "r"(a[0]), "r"(a[1]), "r"(a[2]), "r"(a[3]), "r"(b[0]), "r"(b[1]));
}

// ======================= reductions ==========================================
__device__ __forceinline__ float blockReduceMax(float v, float* sm) {
#pragma unroll
    for (int o = 16; o; o >>= 1) v = fmaxf(v, __shfl_xor_sync(0xffffffffu, v, o));
    if ((threadIdx.x & 31) == 0) sm[threadIdx.x >> 5] = v;
    __syncthreads();
    if (threadIdx.x < 32) {
        float t = (threadIdx.x < 8) ? sm[threadIdx.x] : -3.0e38f;
#pragma unroll
        for (int o = 4; o; o >>= 1) t = fmaxf(t, __shfl_xor_sync(0xffffffffu, t, o));
        if (threadIdx.x == 0) sm[0] = t;
    }
    __syncthreads();
    float r = sm[0];
    __syncthreads();
    return r;
}
__device__ __forceinline__ float blockReduceSum(float v, float* sm) {
#pragma unroll
    for (int o = 16; o; o >>= 1) v += __shfl_xor_sync(0xffffffffu, v, o);
    if ((threadIdx.x & 31) == 0) sm[threadIdx.x >> 5] = v;
    __syncthreads();
    if (threadIdx.x < 32) {
        float t = (threadIdx.x < 8) ? sm[threadIdx.x] : 0.f;
#pragma unroll
        for (int o = 4; o; o >>= 1) t += __shfl_xor_sync(0xffffffffu, t, o);
        if (threadIdx.x == 0) sm[0] = t;
    }
    __syncthreads();
    float r = sm[0];
    __syncthreads();
    return r;
}

// ======================= 1. fused pe + idxT ====================================
__global__ void peidx_kernel(const float* __restrict__ x,
                             const float* __restrict__ mixer,
                             const float* __restrict__ weight,
                             const float* __restrict__ wb,
                             const float* __restrict__ S) {
    __shared__ __align__(16) char sbuf[4352];
    __shared__ int ccnt[32];
    int bid = blockIdx.x, tid = threadIdx.x;
    if (bid < 128) {
        int bp = bid >> 2;
        int b = bp >> 2, p = bp & 3;
        float* s1 = (float*)sbuf;
        float* s2 = s1 + Gc;
        float* sc = (float*)ccnt;
        {
            int g = tid;
            float v1 = 0.f, v2 = 0.f;
            const float* mw1 = mixer + p * 2 * Fc;
            const float* mw2 = mw1 + Fc;
#pragma unroll 8
            for (int f = 0; f < Fc; ++f) {
                float w = weight[((size_t)(p * Fc + f)) * Gc + g];
                v1 = fmaf(mw1[f], w, v1);
                v2 = fmaf(mw2[f], w, v2);
            }
            s1[g] = v1;
            s2[g] = v2;
            if (g == 0) {
                float c1 = 0.f, c2 = 0.f;
                for (int f = 0; f < Fc; ++f) {
                    c1 = fmaf(mw1[f], wb[p * Fc + f], c1);
                    c2 = fmaf(mw2[f], wb[p * Fc + f], c2);
                }
                sc[0] = c1;
                sc[1] = c2;
            }
        }
        __syncthreads();
        int n = (bid & 3) * 256 + tid;
        const float* xb = x + (size_t)b * Gc * Nn + n;
        float a1 = 0.f, a2 = 0.f;
#pragma unroll 8
        for (int g = 0; g < Gc; ++g) {
            float xv = xb[(size_t)g * Nn];
            a1 = fmaf(s1[g], xv, a1);
            a2 = fmaf(s2[g], xv, a2);
        }
        g_e1[bp * Nn + n] = a1 + sc[0];
        g_e2[bp * Nn + n] = a2 + sc[1];
    } else {
        int fb = bid - 128;
        int b = fb >> 5;
        int j0 = (fb & 31) * 32;
        float(*tile)[33] = (float(*)[33])sbuf;
        int tx = tid & 31, ty = tid >> 5;
        if (tid < 32) ccnt[tid] = 0;
        __syncthreads();
        const float* Sb = S + (size_t)b * Nn * Nn;
        for (int it = 0; it < 32; ++it) {
            int i0 = it * 32;
#pragma unroll
            for (int q = 0; q < 4; ++q) {
                int r = ty + q * 8;
                tile[r][tx] = Sb[(size_t)(i0 + r) * Nn + j0 + tx];
            }
            __syncthreads();
            if (tid < 32) {
                int j = j0 + tid;
                int c = ccnt[tid];
                unsigned short* ip = g_idx + ((size_t)b * Nn + j) * MAXS;
#pragma unroll 8
                for (int r = 0; r < 32; ++r) {
                    if (fabsf(tile[r][tid]) > 1e-9f) {
                        if (c < MAXS) ip[c] = (unsigned short)(i0 + r);
                        ++c;
                    }
                }
                ccnt[tid] = c;
            }
            __syncthreads();
        }
        if (tid < 32) g_cnt[b * Nn + j0 + tid] = ccnt[tid] < MAXS ? ccnt[tid] : MAXS;
    }
}

// ======================= 2. ms + cnt-sort =====================================
__global__ void ms_kernel(const float* __restrict__ S) {
    __shared__ float sm[8];
    __shared__ int hist[129];
    __shared__ int hoff[129];
    int i = blockIdx.x, b = blockIdx.y, tid = threadIdx.x;
    if (i == Nn) {
        for (int c = tid; c < 129; c += 256) hist[c] = 0;
        __syncthreads();
        for (int j = tid; j < Nn; j += 256) atomicAdd(&hist[g_cnt[b * Nn + j]], 1);
        __syncthreads();
        if (tid == 0) {
            int acc = 0;
            for (int c = 0; c <= 128; ++c) {
                hoff[c] = acc;
                acc += hist[c];
            }
        }
        __syncthreads();
        for (int j = tid; j < Nn; j += 256) {
            int c = g_cnt[b * Nn + j];
            int pos = atomicAdd(&hoff[c], 1);
            g_jord[b * Nn + pos] = (unsigned short)j;
        }
        return;
    }
    const float* Sr = S + ((size_t)b * Nn + i) * Nn;
    int mk[4];
    float lv[4][4];
    float e2i[4];
#pragma unroll
    for (int p = 0; p < 4; ++p) e2i[p] = g_e2[(b * 4 + p) * Nn + i];
#pragma unroll
    for (int q = 0; q < 4; ++q) {
        int j = tid + q * 256;
        mk[q] = (fabsf(Sr[j]) > 1e-9f);
#pragma unroll
        for (int p = 0; p < 4; ++p) {
            float e = g_e1[(b * 4 + p) * Nn + j] + e2i[p];
            lv[p][q] = e > 0.f ? e : 0.2f * e;
        }
    }
#pragma unroll
    for (int p = 0; p < 4; ++p) {
        float vmax = -3.0e38f;
#pragma unroll
        for (int q = 0; q < 4; ++q)
            if (mk[q]) vmax = fmaxf(vmax, lv[p][q]);
        vmax = blockReduceMax(vmax, sm);
        float sum = 0.f;
#pragma unroll
        for (int q = 0; q < 4; ++q)
            sum += mk[q] ? __expf(lv[p][q] - vmax) : 0.f;
        sum = blockReduceSum(sum, sm);
        if (tid == 0) {
            g_m[(b * 4 + p) * Nn + i] = vmax;
            g_s[(b * 4 + p) * Nn + i] = sum;
        }
    }
}

// ======================= 3. fused fill + split =================================
// bid < 1024: fill (b = bid>>7, sorted pos group); writes g_avi (per bp),
//             packed g_av4 (4 p) and g_ii, zero-padded to group wlim.
// bid >= 1024: x -> xT fp32/hi/lo per b + fw split.
__global__ void fillsplit_kernel(const float* __restrict__ x, const float* __restrict__ fw) {
    __shared__ float t[32][33];
    int bid = blockIdx.x, tid = threadIdx.x;
    if (bid < 1024) {
        int b = bid >> 7;
        int w = tid >> 5, lane = tid & 31;
        int pos = (bid & 127) * 8 + w;
        int grp = pos & ~3;
        const unsigned short* jordb = g_jord + b * Nn;
        int j = jordb[pos];
        int gmax = 0;
#pragma unroll
        for (int q = 0; q < 4; ++q) {
            int cq = g_cnt[b * Nn + jordb[grp + q]];
            gmax = max(gmax, cq);
        }
        int wlim = (gmax + 7) & ~7;
        int cnt = g_cnt[b * Nn + j];
        float e1j[4];
#pragma unroll
        for (int p = 0; p < 4; ++p) e1j[p] = g_e1[(b * 4 + p) * Nn + j];
        const unsigned short* ip = g_idx + ((size_t)b * Nn + j) * MAXS;
        float4* a4p = g_av4 + ((size_t)b * Nn + j) * MAXS;
        int* iip = g_ii + ((size_t)b * Nn + j) * MAXS;
        for (int s = lane; s < wlim; s += 32) {
            float av[4] = {0.f, 0.f, 0.f, 0.f};
            int iv = 0;
            if (s < cnt) {
                iv = ip[s];
#pragma unroll
                for (int p = 0; p < 4; ++p) {
                    int bp = b * 4 + p;
                    float e = e1j[p] + g_e2[bp * Nn + iv];
                    float l = e > 0.f ? e : 0.2f * e;
                    av[p] = __expf(l - g_m[bp * Nn + iv]) / g_s[bp * Nn + iv];
                }
            }
            a4p[s] = make_float4(av[0], av[1], av[2], av[3]);
            iip[s] = iv;
#pragma unroll
            for (int p = 0; p < 4; ++p)
                g_avi[((size_t)(b * 4 + p) * Nn + j) * MAXS + s] =
                    make_float2(av[p], __int_as_float(iv));
        }
    } else {
        int sbid = bid - 1024;
        int b = sbid >> 8;
        int g0 = ((sbid >> 5) & 7) * 32, n0 = (sbid & 31) * 32;
        int tx = tid & 31, ty = tid >> 5;
        const float* xp = x + ((size_t)b * Gc + g0) * Nn + n0;
#pragma unroll
        for (int q = 0; q < 4; ++q) {
            int g = ty + q * 8;
            t[g][tx] = xp[(size_t)g * Nn + tx];
        }
        __syncthreads();
#pragma unroll
        for (int q = 0; q < 4; ++q) {
            int nn = ty + q * 8;
            float v = t[tx][nn];
            __nv_bfloat16 h, l;
            split2(v, h, l);
            size_t o = ((size_t)b * Nn + n0 + nn) * Gc + g0 + tx;
            g_xT[o] = v;
            g_xTh[o] = h;
            g_xTl[o] = l;
        }
        const int FT = Pc * Fc * Kc * Gc;
        int tot = 2048 * 256;
        int gid = sbid * 256 + tid;
        for (int i = gid; i < FT; i += tot) {
            __nv_bfloat16 h, l;
            split2(fw[i], h, l);
            g_fwh[i] = h;
            g_fwl[i] = l;
        }
    }
}

// ======================= 4a. prop1: step 1, all 4 p fused =====================
// CTA = (gb 0..7, y: b=y&7, jh=y>>3), 512 threads. zin = xT slice (shared by p).
// Warp: 4 sorted-adjacent j within its j-half. Per nnz: 1 a4 bcast + 1 i bcast
// + 1 zv LDS.128 + 16 FMA covering all 4 p.
#define P1OFF (Nn * 32 * 4)
#define P1JST 144                       /* a4 j-stride: 16-aligned, distinct banks */
#define P1ABUF (4 * P1JST)              /* 576 per buffer */
#define P1IOFF (2 * P1ABUF)             /* 1152: i region */
#define P1WST (P1IOFF + 2 * 128)        /* 1408 per warp */
#define P1SMEM (P1OFF + 16 * P1WST)     /* 153600 */

__global__ void __launch_bounds__(512, 1)
prop1_kernel() {
    extern __shared__ __align__(16) char psm[];
    float* zin = (float*)psm;
    char* stgb = psm + P1OFF;
    uint32_t sb = smem_u32(psm);
    const int gb = blockIdx.x;
    const int b = blockIdx.y & 7, jh = blockIdx.y >> 3;
    const int tid = threadIdx.x, w = tid >> 5, lane = tid & 31;
    const int jj = lane >> 3, gq = lane & 7;

    const float* src = g_xT + (size_t)b * Nn * Gc + gb * 32;
#pragma unroll
    for (int r = 0; r < 16; ++r) {
        int idx = r * 512 + tid;
        int row = idx >> 3, c4 = idx & 7;
        float4 v = *(const float4*)(src + (size_t)row * Gc + c4 * 4);
        *(float4*)(zin + row * 32 + c4 * 4) = v;
    }
    __syncthreads();

    const uint32_t abase = sb + P1OFF + w * P1WST;
    const uint32_t adst = abase + (lane >> 3) * P1JST + (lane & 7) * 16;
    const uint32_t idst = abase + P1IOFF + (lane >> 1) * 32 + (lane & 1) * 16;
    const unsigned short* jordb = g_jord + b * Nn;

    for (int pos0 = jh * 512 + w * 4; pos0 < jh * 512 + 512; pos0 += 64) {
        int jl = jordb[pos0 + (lane & 3)];
        int cj = g_cnt[b * Nn + jl];
        cj = max(cj, __shfl_xor_sync(0xffffffffu, cj, 1));
        cj = max(cj, __shfl_xor_sync(0xffffffffu, cj, 2));
        int jv = __shfl_sync(0xffffffffu, jl, jj);
        int js_a = __shfl_sync(0xffffffffu, jl, lane >> 3);
        int js_i = __shfl_sync(0xffffffffu, jl, lane >> 1);
        int nch = (cj + 7) >> 3;
        const float4* a4src = g_av4 + ((size_t)b * Nn + js_a) * MAXS;
        const int* iisrc = g_ii + ((size_t)b * Nn + js_i) * MAXS;

        cpa16(adst, a4src + (lane & 7));
        if (lane < 8) cpa16(idst, iisrc + (lane & 1) * 4);
        cpa_commit();
        float4 acc[4];
#pragma unroll
        for (int p = 0; p < 4; ++p) acc[p] = make_float4(0.f, 0.f, 0.f, 0.f);
        for (int c = 0; c < nch; ++c) {
            if (c + 1 < nch) {
                cpa16(adst + ((c + 1) & 1) * P1ABUF, a4src + (c + 1) * 8 + (lane & 7));
                if (lane < 8) cpa16(idst + ((c + 1) & 1) * 128, iisrc + (c + 1) * 8 + (lane & 1) * 4);
                cpa_commit();
                cpa_wait1();
            } else {
                cpa_wait0();
            }
            __syncwarp();
            const float4* abufp = (const float4*)(stgb + w * P1WST + (c & 1) * P1ABUF + jj * P1JST);
            const int* ibufp = (const int*)(stgb + w * P1WST + P1IOFF + (c & 1) * 128 + jj * 32);
#pragma unroll
            for (int q = 0; q < 8; ++q) {
                float4 a4 = abufp[q];
                int i = ibufp[q];
                const float4 zv = *(const float4*)(zin + i * 32 + gq * 4);
                acc[0].x = fmaf(a4.x, zv.x, acc[0].x);
                acc[0].y = fmaf(a4.x, zv.y, acc[0].y);
                acc[0].z = fmaf(a4.x, zv.z, acc[0].z);
                acc[0].w = fmaf(a4.x, zv.w, acc[0].w);
                acc[1].x = fmaf(a4.y, zv.x, acc[1].x);
                acc[1].y = fmaf(a4.y, zv.y, acc[1].y);
                acc[1].z = fmaf(a4.y, zv.z, acc[1].z);
                acc[1].w = fmaf(a4.y, zv.w, acc[1].w);
                acc[2].x = fmaf(a4.z, zv.x, acc[2].x);
                acc[2].y = fmaf(a4.z, zv.y, acc[2].y);
                acc[2].z = fmaf(a4.z, zv.z, acc[2].z);
                acc[2].w = fmaf(a4.z, zv.w, acc[2].w);
                acc[3].x = fmaf(a4.w, zv.x, acc[3].x);
                acc[3].y = fmaf(a4.w, zv.y, acc[3].y);
                acc[3].z = fmaf(a4.w, zv.z, acc[3].z);
                acc[3].w = fmaf(a4.w, zv.w, acc[3].w);
            }
            __syncwarp();
        }
#pragma unroll
        for (int p = 0; p < 4; ++p) {
            size_t o = ((size_t)(b * 4 + p) * Nn + jv) * Nn + Gc + gb * 32 + gq * 4;
            *(float4*)(g_zf + o) = acc[p];
            __nv_bfloat16 h0, l0, h1, l1, h2, l2, h3, l3;
            split2(acc[p].x, h0, l0);
            split2(acc[p].y, h1, l1);
            split2(acc[p].z, h2, l2);
            split2(acc[p].w, h3, l3);
            __nv_bfloat162 ph01, ph23, pl01, pl23;
            ph01.x = h0; ph01.y = h1; ph23.x = h2; ph23.y = h3;
            pl01.x = l0; pl01.y = l1; pl23.x = l2; pl23.y = l3;
            *(__nv_bfloat162*)(g_zh + o) = ph01;
            *(__nv_bfloat162*)(g_zh + o + 2) = ph23;
            *(__nv_bfloat162*)(g_zl + o) = pl01;
            *(__nv_bfloat162*)(g_zl + o + 2) = pl23;
        }
    }
}

// ======================= 4b. prop: steps 2-3 (per-bp) =========================
#define PSTG_OFF (Nn * 32 * 4)
#define JSTRIDE 80
#define BUFB (4 * JSTRIDE)
#define WSTG (2 * BUFB)
#define PSMEM (PSTG_OFF + 16 * WSTG)

__global__ void __launch_bounds__(512, 1)
prop_kernel(int ks) {
    extern __shared__ __align__(16) char psm[];
    float* zin = (float*)psm;
    const char* stgb = psm + PSTG_OFF;
    uint32_t sb = smem_u32(psm);
    const int bp = blockIdx.y, b = bp >> 2, gb = blockIdx.x;
    const int tid = threadIdx.x, w = tid >> 5, lane = tid & 31;
    const int jj = lane >> 3, gq = lane & 7;
    const bool stager = (gq < 4);
    const size_t NN = (size_t)Nn * Nn;

    const float* src = g_zf + (size_t)bp * NN + (size_t)(ks - 1) * Gc + (size_t)gb * 32;
#pragma unroll
    for (int r = 0; r < 16; ++r) {
        int idx = r * 512 + tid;
        int row = idx >> 3, c4 = idx & 7;
        float4 v = *(const float4*)(src + (size_t)row * Nn + c4 * 4);
        *(float4*)(zin + row * 32 + c4 * 4) = v;
    }
    __syncthreads();

    const uint32_t stga = sb + PSTG_OFF + w * WSTG + jj * JSTRIDE + (gq & 3) * 16;
    const unsigned short* jordb = g_jord + b * Nn;

    for (int g0 = w * 4; g0 < Nn; g0 += 64) {
        int jl = jordb[g0 + (lane & 3)];
        int cj = g_cnt[b * Nn + jl];
        cj = max(cj, __shfl_xor_sync(0xffffffffu, cj, 1));
        cj = max(cj, __shfl_xor_sync(0xffffffffu, cj, 2));
        int jv = __shfl_sync(0xffffffffu, jl, jj);
        int nch = (cj + 7) >> 3;
        const float2* arow = g_avi + ((size_t)bp * Nn + jv) * MAXS;

        if (stager) cpa16(stga, arow + (gq & 3) * 2);
        cpa_commit();
        float4 acc0 = make_float4(0.f, 0.f, 0.f, 0.f);
        float4 acc1 = make_float4(0.f, 0.f, 0.f, 0.f);
        for (int c = 0; c < nch; ++c) {
            if (c + 1 < nch) {
                if (stager) cpa16(stga + ((c + 1) & 1) * BUFB, arow + (c + 1) * 8 + (gq & 3) * 2);
                cpa_commit();
                cpa_wait1();
            } else {
                cpa_wait0();
            }
            __syncwarp();
            const float2* bufp = (const float2*)(stgb + w * WSTG + (c & 1) * BUFB + jj * JSTRIDE);
#pragma unroll
            for (int q = 0; q < 8; ++q) {
                float2 av = bufp[q];
                int i = __float_as_int(av.y);
                float a = av.x;
                const float4 zv = *(const float4*)(zin + i * 32 + gq * 4);
                if (q & 1) {
                    acc1.x = fmaf(a, zv.x, acc1.x);
                    acc1.y = fmaf(a, zv.y, acc1.y);
                    acc1.z = fmaf(a, zv.z, acc1.z);
                    acc1.w = fmaf(a, zv.w, acc1.w);
                } else {
                    acc0.x = fmaf(a, zv.x, acc0.x);
                    acc0.y = fmaf(a, zv.y, acc0.y);
                    acc0.z = fmaf(a, zv.z, acc0.z);
                    acc0.w = fmaf(a, zv.w, acc0.w);
                }
            }
            __syncwarp();
        }
        float4 acc = make_float4(acc0.x + acc1.x, acc0.y + acc1.y,
                                 acc0.z + acc1.z, acc0.w + acc1.w);
        size_t o = ((size_t)bp * Nn + jv) * Nn + (size_t)ks * Gc + gb * 32 + gq * 4;
        *(float4*)(g_zf + o) = acc;
        __nv_bfloat16 h0, l0, h1, l1, h2, l2, h3, l3;
        split2(acc.x, h0, l0);
        split2(acc.y, h1, l1);
        split2(acc.z, h2, l2);
        split2(acc.w, h3, l3);
        __nv_bfloat162 ph01, ph23, pl01, pl23;
        ph01.x = h0; ph01.y = h1; ph23.x = h2; ph23.y = h3;
        pl01.x = l0; pl01.y = l1; pl23.x = l2; pl23.y = l3;
        *(__nv_bfloat162*)(g_zh + o) = ph01;
        *(__nv_bfloat162*)(g_zh + o + 2) = ph23;
        *(__nv_bfloat162*)(g_zl + o) = pl01;
        *(__nv_bfloat162*)(g_zl + o + 2) = pl23;
    }
}

// ======================= 5. HMMA filter GEMM ===================================
#define TBK 32
#define NCH (Nn / TBK)
#define ASTG 16384
#define BSTG 16384
#define STG (ASTG + BSTG)
#define NSTAGE 3
#define SMEM_GEMM (NSTAGE * STG)

__global__ void __launch_bounds__(256, 2)
mma_gemm(const float* __restrict__ bias, float* __restrict__ out) {
    extern __shared__ __align__(1024) char smem[];
    uint32_t sb = smem_u32(smem);
    const int bp = blockIdx.z, p = bp & 3, b = bp >> 2;
    const int m0 = blockIdx.y * 128, n0 = blockIdx.x * 128;
    const int tid = threadIdx.x, wid = tid >> 5, lane = tid & 31;
    const int warp_m = wid >> 2, warp_n = wid & 3;
    const size_t NN = (size_t)Nn * Nn;

    const __nv_bfloat16* Ah = g_fwh + (size_t)p * Fc * Nn;
    const __nv_bfloat16* Al = g_fwl + (size_t)p * Fc * Nn;
    const __nv_bfloat16* Bh1 = g_zh + (size_t)bp * NN;
    const __nv_bfloat16* Bl1 = g_zl + (size_t)bp * NN;
    const __nv_bfloat16* Bh0 = g_xTh + (size_t)b * Nn * Gc;
    const __nv_bfloat16* Bl0 = g_xTl + (size_t)b * Nn * Gc;

    float acc[4][4][4];
#pragma unroll
    for (int i = 0; i < 4; ++i)
#pragma unroll
        for (int j = 0; j < 4; ++j)
#pragma unroll
            for (int q = 0; q < 4; ++q) acc[i][j][q] = 0.f;

    auto load_stage = [&](int c, int s) {
        uint32_t base = sb + s * STG;
        int k0 = c * TBK;
        bool sl0 = (c < 8);
        const __nv_bfloat16* bh = sl0 ? Bh0 : Bh1;
        const __nv_bfloat16* bl = sl0 ? Bl0 : Bl1;
        int bstride = sl0 ? Gc : Nn;
#pragma unroll
        for (int i = 0; i < 4; ++i) {
            int idx = i * 256 + tid;
            int r = idx >> 3, ch = idx & 7;
            const __nv_bfloat16* srcp = ((ch < 4) ? Ah : Al) + (size_t)(m0 + r) * Nn + k0 + (ch & 3) * 8;
            cpa16(base + SWZ(r * 128 + ch * 16), srcp);
        }
#pragma unroll
        for (int i = 0; i < 4; ++i) {
            int idx = i * 256 + tid;
            int r = idx >> 3, ch = idx & 7;
            const __nv_bfloat16* srcp = ((ch < 4) ? bh : bl) + (size_t)(n0 + r) * bstride + k0 + (ch & 3) * 8;
            cpa16(base + ASTG + SWZ(r * 128 + ch * 16), srcp);
        }
        cpa_commit();
    };

    const int a_row = (lane & 7) + ((lane >> 3) & 1) * 8;
    const int a_k16 = lane >> 4;
    const int b_row = (lane & 7);
    const int b_par = (lane >> 3) & 1;

    load_stage(0, 0);
    load_stage(1, 1);
    for (int c = 0; c < NCH; ++c) {
        if (c + 2 < NCH) {
            load_stage(c + 2, (c + 2) % NSTAGE);
            cpa_wait2();
        } else if (c + 1 < NCH) {
            cpa_wait1();
        } else {
            cpa_wait0();
        }
        __syncthreads();
        uint32_t Abase = sb + (c % NSTAGE) * STG;
        uint32_t Bbase = Abase + ASTG;
#pragma unroll
        for (int s = 0; s < 2; ++s) {
            uint32_t bh2[4][2], bl2[4][2];
#pragma unroll
            for (int o = 0; o < 4; ++o) {
                int row = warp_n * 32 + o * 8 + b_row;
                int chk = s * 2 + b_par;
                ldm_x2(bh2[o][0], bh2[o][1], Bbase + SWZ(row * 128 + chk * 16));
                ldm_x2(bl2[o][0], bl2[o][1], Bbase + SWZ(row * 128 + 64 + chk * 16));
            }
            uint32_t ah[4][4], al[4][4];
#pragma unroll
            for (int mt = 0; mt < 4; ++mt) {
                int row = warp_m * 64 + mt * 16 + a_row;
                int chh = s * 2 + a_k16;
                ldm_x4(ah[mt][0], ah[mt][1], ah[mt][2], ah[mt][3],
                       Abase + SWZ(row * 128 + chh * 16));
                ldm_x4(al[mt][0], al[mt][1], al[mt][2], al[mt][3],
                       Abase + SWZ(row * 128 + 64 + chh * 16));
            }
#pragma unroll
            for (int mt = 0; mt < 4; ++mt)
#pragma unroll
                for (int o = 0; o < 4; ++o) mma16816(acc[mt][o], ah[mt], bh2[o]);
#pragma unroll
            for (int mt = 0; mt < 4; ++mt)
#pragma unroll
                for (int o = 0; o < 4; ++o) mma16816(acc[mt][o], ah[mt], bl2[o]);
#pragma unroll
            for (int mt = 0; mt < 4; ++mt)
#pragma unroll
                for (int o = 0; o < 4; ++o) mma16816(acc[mt][o], al[mt], bh2[o]);
        }
        __syncthreads();
    }

    float* C = out + (size_t)bp * Fc * Nn;
    const int r_base = m0 + warp_m * 64 + (lane >> 2);
    const int c_base = n0 + warp_n * 32 + (lane & 3) * 2;
#pragma unroll
    for (int mt = 0; mt < 4; ++mt)
#pragma unroll
        for (int o = 0; o < 4; ++o) {
#pragma unroll
            for (int h = 0; h < 2; ++h) {
                int r = r_base + mt * 16 + h * 8;
                int cc = c_base + o * 8;
                float bv = bias[r];
                float t0 = acc[mt][o][2 * h] + bv;
                float t1 = acc[mt][o][2 * h + 1] + bv;
                t0 = t0 > 0.f ? t0 : 0.01f * t0;
                t1 = t1 > 0.f ? t1 : 0.01f * t1;
                *(float2*)(C + (size_t)r * Nn + cc) = make_float2(t0, t1);
            }
        }
}

// ======================= launch ================================================
extern "C" void kernel_launch(void* const* d_in, const int* in_sizes, int n_in,
                              void* d_out, int out_size) {
    const float* x      = (const float*)d_in[0];
    const float* mixer  = (const float*)d_in[1];
    const float* weight = (const float*)d_in[2];
    const float* wb     = (const float*)d_in[3];
    const float* fw     = (const float*)d_in[4];
    const float* bias   = (const float*)d_in[5];
    const float* S      = (const float*)d_in[6];
    float* out = (float*)d_out;

    cudaFuncSetAttribute(mma_gemm, cudaFuncAttributeMaxDynamicSharedMemorySize, SMEM_GEMM);
    cudaFuncSetAttribute(prop_kernel, cudaFuncAttributeMaxDynamicSharedMemorySize, PSMEM);
    cudaFuncSetAttribute(prop1_kernel, cudaFuncAttributeMaxDynamicSharedMemorySize, P1SMEM);

    peidx_kernel<<<384, 256>>>(x, mixer, weight, wb, S);       // 1
    ms_kernel<<<dim3(Nn + 1, Bc), 256>>>(S);                   // 2
    fillsplit_kernel<<<3072, 256>>>(x, fw);                    // 3
    prop1_kernel<<<dim3(8, 16), 512, P1SMEM>>>();              // 4 (profiled)
    prop_kernel<<<dim3(8, NBP), 512, PSMEM>>>(2);              // 5
    prop_kernel<<<dim3(8, NBP), 512, PSMEM>>>(3);              // 6
    mma_gemm<<<dim3(Nn / 128, Fc / 128, NBP), 256, SMEM_GEMM>>>(bias, out);  // 7
}